// round 11
// baseline (speedup 1.0000x reference)
#include <cuda_runtime.h>
#include <cuda_bf16.h>
#include <cstdint>

#define EPSV 1e-5f
#define BGR 4096
#define NCLS 7
#define NTHR 320
typedef unsigned long long u64;
typedef unsigned int u32;

// ================= device globals =================
__device__ float d_w1[32], d_b1[32];
__device__ float d_W2[32*64],   d_B2[64];
__device__ float d_W3[64*64],   d_B3[64];
__device__ float d_W4[64*64],   d_B4[64];
__device__ float d_W5T[128*64], d_B5[128];   // [out(128)][in(64)]
__device__ float d_W6[128*128], d_B6[128];
__device__ float d_F1[128*64],  d_FB1[64];
__device__ float d_F2[64*32],   d_FB2[32];
__device__ float d_F3[32*NCLS], d_FB3[NCLS];
__device__ float d_g0[128];
__device__ float d_sums[BGR*128];
__device__ float d_cnts[BGR];
__device__ int   d_tile_ctr;

// interleaved fragment streams: per (kf,nf,lane) one ulonglong2 = {hi_frag, lo_frag}
__device__ ulonglong2 g_S2[512];    // K=32 (KF=2),  N=64 (NF=8)
__device__ ulonglong2 g_S3[1024];   // K=64, N=64
__device__ ulonglong2 g_S4[1024];   // K=64, N=64
__device__ ulonglong2 g_S5[2048];   // K=64, N=128
__device__ ulonglong2 g_S6[4096];   // K=128, N=128

__device__ __forceinline__ float bn_a(const float* bn, int c, int i){ return bn[0*c+i]*rsqrtf(bn[3*c+i]+EPSV); }
__device__ __forceinline__ float bn_c(const float* bn, int c, int i, float a){ return bn[1*c+i]-bn[2*c+i]*a; }

// ================= prep: fold BNs (fp32, validated) =================
__global__ void prep_kernel(
    const float* w1, const float* b1, const float* bn1,
    const float* w2, const float* b2, const float* bn2,
    const float* c1aw, const float* c1ab,
    const float* c1bw, const float* c1bb, const float* cbn1,
    const float* c2aw, const float* c2ab,
    const float* c2bw, const float* c2bb, const float* cbn2,
    const float* f1w, const float* f1b, const float* fbn1,
    const float* f2w, const float* f2b, const float* fbn2,
    const float* f3w, const float* f3b)
{
    int t = threadIdx.x;
    for (int i=t;i<32;i+=256){ d_w1[i]=w1[i]; d_b1[i]=b1[i]; }
    for (int i=t;i<32*64;i+=256){ int k=i>>6; d_W2[i]=bn_a(bn1,32,k)*w2[i]; }
    for (int j=t;j<64;j+=256){ float s=b2[j];
        for(int k=0;k<32;k++){float a=bn_a(bn1,32,k); s+=bn_c(bn1,32,k,a)*w2[k*64+j];}
        d_B2[j]=s; }
    for (int i=t;i<64*64;i+=256){ int k=i>>6; d_W3[i]=bn_a(bn2,64,k)*c1aw[i]; }
    for (int j=t;j<64;j+=256){ float s=c1ab[j];
        for(int k=0;k<64;k++){float a=bn_a(bn2,64,k); s+=bn_c(bn2,64,k,a)*c1aw[k*64+j];}
        d_B3[j]=s; }
    for (int i=t;i<64*64;i+=256) d_W4[i]=c1bw[i];
    for (int j=t;j<64;j+=256)    d_B4[j]=c1bb[j];
    for (int i=t;i<128*64;i+=256){ int k=i>>6, m=i&63; d_W5T[i]=bn_a(cbn1,64,m)*c2aw[m*128+k]; }
    for (int k=t;k<128;k+=256){ float s=c2ab[k];
        for(int m=0;m<64;m++){float a=bn_a(cbn1,64,m); s+=bn_c(cbn1,64,m,a)*c2aw[m*128+k];}
        d_B5[k]=s; }
    for (int i=t;i<128*128;i+=256) d_W6[i]=c2bw[i];
    for (int j=t;j<128;j+=256)     d_B6[j]=c2bb[j];
    for (int i=t;i<128*64;i+=256){ int k=i>>6; d_F1[i]=bn_a(cbn2,128,k)*f1w[i]; }
    for (int j=t;j<64;j+=256){ float s=f1b[j];
        for(int k=0;k<128;k++){float a=bn_a(cbn2,128,k); s+=bn_c(cbn2,128,k,a)*f1w[k*64+j];}
        d_FB1[j]=s; }
    for (int k=t;k<128;k+=256){ float a=bn_a(cbn2,128,k); d_g0[k]=-bn_c(cbn2,128,k,a)/a; }
    for (int i=t;i<64*32;i+=256){ int k=i>>5; d_F2[i]=bn_a(fbn1,64,k)*f2w[i]; }
    for (int j=t;j<32;j+=256){ float s=f2b[j];
        for(int k=0;k<64;k++){float a=bn_a(fbn1,64,k); s+=bn_c(fbn1,64,k,a)*f2w[k*32+j];}
        d_FB2[j]=s; }
    for (int i=t;i<32*NCLS;i+=256){ int k=i/NCLS; d_F3[i]=bn_a(fbn2,32,k)*f3w[i]; }
    for (int j=t;j<NCLS;j+=256){ float s=f3b[j];
        for(int k=0;k<32;k++){float a=bn_a(fbn2,32,k); s+=bn_c(fbn2,32,k,a)*f3w[k*NCLS+j];}
        d_FB3[j]=s; }
}

// ================= pack: weights -> interleaved hi/lo B-fragment streams =================
__device__ __forceinline__ u32 pkbf(float a, float b){
    __nv_bfloat16 ha=__float2bfloat16(a), hb=__float2bfloat16(b);
    return (u32)__bfloat16_as_ushort(ha) | ((u32)__bfloat16_as_ushort(hb)<<16);
}
__device__ void pack_stream(ulonglong2* S, const float* W, int KF, int NF, int N,
                            bool tr, int ld, int tid, int nthr)
{
    int tot = KF*NF*32;
    for (int i=tid;i<tot;i+=nthr){
        int lane = i&31, nf=(i>>5)%NF, kf=i/(32*NF);
        int nn = nf*8 + (lane>>2);
        int k0 = kf*16 + (lane&3)*2;
        float v[4];
        int ks[4]={k0,k0+1,k0+8,k0+9};
        #pragma unroll
        for (int j=0;j<4;j++) v[j] = tr ? W[nn*ld + ks[j]] : W[ks[j]*N + nn];
        u32 h0 = pkbf(v[0],v[1]), h1 = pkbf(v[2],v[3]);
        float l[4];
        #pragma unroll
        for (int j=0;j<4;j++) l[j] = v[j] - __bfloat162float(__float2bfloat16(v[j]));
        u32 L0 = pkbf(l[0],l[1]), L1 = pkbf(l[2],l[3]);
        ulonglong2 e;
        e.x = (u64)h0 | ((u64)h1<<32);
        e.y = (u64)L0 | ((u64)L1<<32);
        S[(kf*NF+nf)*32+lane] = e;
    }
}
__global__ void pack_kernel(){
    int t = threadIdx.x;
    pack_stream(g_S2, d_W2,  2, 8,  64, false, 0,  t,256);
    pack_stream(g_S3, d_W3,  4, 8,  64, false, 0,  t,256);
    pack_stream(g_S4, d_W4,  4, 8,  64, false, 0,  t,256);
    pack_stream(g_S5, d_W5T, 4,16, 128, true, 64,  t,256);
    pack_stream(g_S6, d_W6,  8,16, 128, false, 0,  t,256);
}

__global__ void zero_kernel(){
    int i = blockIdx.x*blockDim.x + threadIdx.x;
    if (i < BGR*128) d_sums[i] = 0.f;
    if (i < BGR)     d_cnts[i] = 0.f;
    if (i == 0)      d_tile_ctr = 0;
}

// ================= node kernel =================
#define O2 0
#define O3 512
#define O4 1536
#define O5 2560
#define O6 4608
#define SMV 8704
#define BIAS_F (SMV*4)
#define W1_F   (BIAS_F+448)
#define NODE_SMEM_BYTES ((W1_F+64)*4)

__device__ __forceinline__ void mma_bf16(float& c0,float& c1,float& c2,float& c3,
                                         u32 a0,u32 a1,u32 a2,u32 a3, u32 b0, u32 b1){
    asm volatile("mma.sync.aligned.m16n8k16.row.col.f32.bf16.bf16.f32 "
        "{%0,%1,%2,%3},{%4,%5,%6,%7},{%8,%9},{%0,%1,%2,%3};"
        : "+f"(c0),"+f"(c1),"+f"(c2),"+f"(c3)
        : "r"(a0),"r"(a1),"r"(a2),"r"(a3),"r"(b0),"r"(b1));
}
__device__ __forceinline__ u32 pack_hi(float v0, float v1){
    return (u32)__bfloat16_as_ushort(__float2bfloat16(v0))
         | ((u32)__bfloat16_as_ushort(__float2bfloat16(v1))<<16);
}
#define MMA4(C, A, B) mma_bf16((C)[0],(C)[1],(C)[2],(C)[3],(A)[0],(A)[1],(A)[2],(A)[3],(u32)(B),(u32)((B)>>32))

// Dual row-block layer, nf-QUAD streaming: one B-fragment LDS.128 feeds 4 MMAs
// (hi/lo x 2 row-blocks). 8 C-fragments (16 chains incl. both blocks) live at
// a time -> same-accumulator distance 8. Per-accumulator order (kf asc,
// hi before lo) identical to R9/R10 -> bit-identical results.
template<int KF,int NF>
__device__ __forceinline__ void layer_cv(const ulonglong2* __restrict__ S,
    const float* __restrict__ bias,
    const u32 A0[][4], const u32 A1[][4], u32 O0[][4], u32 O1[][4], int lane)
{
    int m2 = (lane&3)*2;
    #pragma unroll
    for (int nf0=0; nf0<NF; nf0+=4){
        float Ca0[4],Cb0[4],Cc0[4],Cd0[4];
        float Ca1[4],Cb1[4],Cc1[4],Cd1[4];
        {
            float2 ba = *(const float2*)(bias + (nf0  )*8 + m2);
            float2 bb = *(const float2*)(bias + (nf0+1)*8 + m2);
            float2 bc = *(const float2*)(bias + (nf0+2)*8 + m2);
            float2 bd = *(const float2*)(bias + (nf0+3)*8 + m2);
            Ca0[0]=ba.x;Ca0[1]=ba.y;Ca0[2]=ba.x;Ca0[3]=ba.y;
            Ca1[0]=ba.x;Ca1[1]=ba.y;Ca1[2]=ba.x;Ca1[3]=ba.y;
            Cb0[0]=bb.x;Cb0[1]=bb.y;Cb0[2]=bb.x;Cb0[3]=bb.y;
            Cb1[0]=bb.x;Cb1[1]=bb.y;Cb1[2]=bb.x;Cb1[3]=bb.y;
            Cc0[0]=bc.x;Cc0[1]=bc.y;Cc0[2]=bc.x;Cc0[3]=bc.y;
            Cc1[0]=bc.x;Cc1[1]=bc.y;Cc1[2]=bc.x;Cc1[3]=bc.y;
            Cd0[0]=bd.x;Cd0[1]=bd.y;Cd0[2]=bd.x;Cd0[3]=bd.y;
            Cd1[0]=bd.x;Cd1[1]=bd.y;Cd1[2]=bd.x;Cd1[3]=bd.y;
        }
        #pragma unroll
        for (int kf=0;kf<KF;kf++){
            ulonglong2 fA = S[(kf*NF+nf0  )*32+lane];
            ulonglong2 fB = S[(kf*NF+nf0+1)*32+lane];
            ulonglong2 fC = S[(kf*NF+nf0+2)*32+lane];
            ulonglong2 fD = S[(kf*NF+nf0+3)*32+lane];
            MMA4(Ca0, A0[kf], fA.x); MMA4(Ca1, A1[kf], fA.x);
            MMA4(Cb0, A0[kf], fB.x); MMA4(Cb1, A1[kf], fB.x);
            MMA4(Cc0, A0[kf], fC.x); MMA4(Cc1, A1[kf], fC.x);
            MMA4(Cd0, A0[kf], fD.x); MMA4(Cd1, A1[kf], fD.x);
            MMA4(Ca0, A0[kf], fA.y); MMA4(Ca1, A1[kf], fA.y);
            MMA4(Cb0, A0[kf], fB.y); MMA4(Cb1, A1[kf], fB.y);
            MMA4(Cc0, A0[kf], fC.y); MMA4(Cc1, A1[kf], fC.y);
            MMA4(Cd0, A0[kf], fD.y); MMA4(Cd1, A1[kf], fD.y);
        }
        int g = nf0>>1;
        O0[g][0]=pack_hi(fmaxf(Ca0[0],0.f),fmaxf(Ca0[1],0.f));
        O0[g][1]=pack_hi(fmaxf(Ca0[2],0.f),fmaxf(Ca0[3],0.f));
        O0[g][2]=pack_hi(fmaxf(Cb0[0],0.f),fmaxf(Cb0[1],0.f));
        O0[g][3]=pack_hi(fmaxf(Cb0[2],0.f),fmaxf(Cb0[3],0.f));
        O0[g+1][0]=pack_hi(fmaxf(Cc0[0],0.f),fmaxf(Cc0[1],0.f));
        O0[g+1][1]=pack_hi(fmaxf(Cc0[2],0.f),fmaxf(Cc0[3],0.f));
        O0[g+1][2]=pack_hi(fmaxf(Cd0[0],0.f),fmaxf(Cd0[1],0.f));
        O0[g+1][3]=pack_hi(fmaxf(Cd0[2],0.f),fmaxf(Cd0[3],0.f));
        O1[g][0]=pack_hi(fmaxf(Ca1[0],0.f),fmaxf(Ca1[1],0.f));
        O1[g][1]=pack_hi(fmaxf(Ca1[2],0.f),fmaxf(Ca1[3],0.f));
        O1[g][2]=pack_hi(fmaxf(Cb1[0],0.f),fmaxf(Cb1[1],0.f));
        O1[g][3]=pack_hi(fmaxf(Cb1[2],0.f),fmaxf(Cb1[3],0.f));
        O1[g+1][0]=pack_hi(fmaxf(Cc1[0],0.f),fmaxf(Cc1[1],0.f));
        O1[g+1][1]=pack_hi(fmaxf(Cc1[2],0.f),fmaxf(Cc1[3],0.f));
        O1[g+1][2]=pack_hi(fmaxf(Cd1[0],0.f),fmaxf(Cd1[1],0.f));
        O1[g+1][3]=pack_hi(fmaxf(Cd1[2],0.f),fmaxf(Cd1[3],0.f));
    }
}

// reduce one C-fragment pair (cols [colbase,colbase+16)) for one 16-row block
__device__ __forceinline__ void reduce2(const float Ca[4], const float Cb[4],
    bool v0r, bool v1r, int b0i, int b1i, int lane, int m, int colbase, bool addcnt)
{
    const unsigned FULL = 0xffffffffu;
    bool uni = __all_sync(FULL, v0r && v1r);
    int bf_ = __shfl_sync(FULL, b0i, 0);
    uni = uni && __all_sync(FULL, (b0i==bf_) && (b1i==bf_));
    if (uni){
        float* dst = d_sums + (size_t)bf_*128 + colbase;
        float s0 = fmaxf(Ca[0],0.f) + fmaxf(Ca[2],0.f);
        float s1 = fmaxf(Ca[1],0.f) + fmaxf(Ca[3],0.f);
        float t0 = fmaxf(Cb[0],0.f) + fmaxf(Cb[2],0.f);
        float t1 = fmaxf(Cb[1],0.f) + fmaxf(Cb[3],0.f);
        s0 += __shfl_xor_sync(FULL,s0,4);  s1 += __shfl_xor_sync(FULL,s1,4);
        t0 += __shfl_xor_sync(FULL,t0,4);  t1 += __shfl_xor_sync(FULL,t1,4);
        s0 += __shfl_xor_sync(FULL,s0,8);  s1 += __shfl_xor_sync(FULL,s1,8);
        t0 += __shfl_xor_sync(FULL,t0,8);  t1 += __shfl_xor_sync(FULL,t1,8);
        s0 += __shfl_xor_sync(FULL,s0,16); s1 += __shfl_xor_sync(FULL,s1,16);
        t0 += __shfl_xor_sync(FULL,t0,16); t1 += __shfl_xor_sync(FULL,t1,16);
        if (lane < 4){
            atomicAdd(dst + 2*lane,     s0);
            atomicAdd(dst + 2*lane + 1, s1);
            atomicAdd(dst + 8 + 2*lane,     t0);
            atomicAdd(dst + 8 + 2*lane + 1, t1);
        }
        if (addcnt && lane==0) atomicAdd(&d_cnts[bf_], 16.f);
    } else {
        unsigned vb0 = __ballot_sync(FULL, v0r && m==0);
        unsigned vb1 = __ballot_sync(FULL, v1r && m==0);
        unsigned rem = 0;
        #pragma unroll
        for (int rr=0; rr<8; rr++){
            if ((vb0>>(4*rr))&1) rem |= 1u<<rr;
            if ((vb1>>(4*rr))&1) rem |= 1u<<(rr+8);
        }
        while (rem){
            int j = __ffs(rem)-1;
            int bt = (j<8) ? __shfl_sync(FULL,b0i,j*4) : __shfl_sync(FULL,b1i,(j-8)*4);
            bool p0 = (b0i==bt), p1 = (b1i==bt);
            float* dst = d_sums + (size_t)bt*128 + colbase;
            float s0 = (p0?fmaxf(Ca[0],0.f):0.f) + (p1?fmaxf(Ca[2],0.f):0.f);
            float s1 = (p0?fmaxf(Ca[1],0.f):0.f) + (p1?fmaxf(Ca[3],0.f):0.f);
            float t0 = (p0?fmaxf(Cb[0],0.f):0.f) + (p1?fmaxf(Cb[2],0.f):0.f);
            float t1 = (p0?fmaxf(Cb[1],0.f):0.f) + (p1?fmaxf(Cb[3],0.f):0.f);
            s0 += __shfl_xor_sync(FULL,s0,4);  s1 += __shfl_xor_sync(FULL,s1,4);
            t0 += __shfl_xor_sync(FULL,t0,4);  t1 += __shfl_xor_sync(FULL,t1,4);
            s0 += __shfl_xor_sync(FULL,s0,8);  s1 += __shfl_xor_sync(FULL,s1,8);
            t0 += __shfl_xor_sync(FULL,t0,8);  t1 += __shfl_xor_sync(FULL,t1,8);
            s0 += __shfl_xor_sync(FULL,s0,16); s1 += __shfl_xor_sync(FULL,s1,16);
            t0 += __shfl_xor_sync(FULL,t0,16); t1 += __shfl_xor_sync(FULL,t1,16);
            if (lane < 4){
                atomicAdd(dst + 2*lane,     s0);
                atomicAdd(dst + 2*lane + 1, s1);
                atomicAdd(dst + 8 + 2*lane,     t0);
                atomicAdd(dst + 8 + 2*lane + 1, t1);
            }
            unsigned m0 = __ballot_sync(FULL, p0 && m==0);
            unsigned m1 = __ballot_sync(FULL, p1 && m==0);
            if (addcnt && lane==0) atomicAdd(&d_cnts[bt], (float)(__popc(m0)+__popc(m1)));
            unsigned clr = 0;
            #pragma unroll
            for (int rr=0; rr<8; rr++){
                if ((m0>>(4*rr))&1) clr |= 1u<<rr;
                if ((m1>>(4*rr))&1) clr |= 1u<<(rr+8);
            }
            rem &= ~clr;
        }
    }
}

__global__ void __launch_bounds__(NTHR,1)
node_kernel(const float* __restrict__ x, const int* __restrict__ batch, int n)
{
    extern __shared__ float smf[];
    ulonglong2* sv = (ulonglong2*)smf;
    int tid = threadIdx.x;
    int lane = tid & 31, w = tid >> 5;

    for (int i=tid;i<512;i+=NTHR)  sv[O2+i]=g_S2[i];
    for (int i=tid;i<1024;i+=NTHR){ sv[O3+i]=g_S3[i]; sv[O4+i]=g_S4[i]; }
    for (int i=tid;i<2048;i+=NTHR) sv[O5+i]=g_S5[i];
    for (int i=tid;i<4096;i+=NTHR) sv[O6+i]=g_S6[i];
    { float* bias = smf + BIAS_F;
      for (int i=tid;i<64;i+=NTHR){ bias[i]=d_B2[i]; bias[64+i]=d_B3[i]; bias[128+i]=d_B4[i]; }
      for (int i=tid;i<128;i+=NTHR){ bias[192+i]=d_B5[i]; bias[320+i]=d_B6[i]; }
      float* w1s = smf + W1_F;
      for (int i=tid;i<32;i+=NTHR){ w1s[i]=d_w1[i]; w1s[32+i]=d_b1[i]; } }
    __syncthreads();

    int r = lane>>2, m = lane&3;

    // static warp-level task assignment: 32 rows per task (2 blocks), no barriers
    const int ntasks = (n + 31) >> 5;
    const int nwarps = gridDim.x * (NTHR/32);
    int gw = blockIdx.x * (NTHR/32) + w;

    for (int task = gw; task < ntasks; task += nwarps){
        int base = task*32;
        int e0 = base + r,      e1 = e0 + 8;
        int e2 = base + 16 + r, e3 = e2 + 8;
        bool v0r = e0 < n, v1r = e1 < n, v2r = e2 < n, v3r = e3 < n;
        float x0 = v0r ? x[e0] : 0.f;
        float x1 = v1r ? x[e1] : 0.f;
        float x2 = v2r ? x[e2] : 0.f;
        float x3 = v3r ? x[e3] : 0.f;
        int b0i = v0r ? batch[e0] : -1;
        int b1i = v1r ? batch[e1] : -1;
        int b2i = v2r ? batch[e2] : -1;
        int b3i = v3r ? batch[e3] : -1;

        u32 I0[2][4], I1[2][4];           // layer1 output (KF=2)
        u32 P0[4][4], P1[4][4];           // ping
        u32 Q0[4][4], Q1[4][4];           // pong
        u32 A0[8][4], A1[8][4];           // layer5 output (KF=8 for L6)

        // --- layer1: 1 -> 32 into fragments for both blocks ---
        {
            const float* w1s = smf + W1_F;
            const float* b1s = w1s + 32;
            #pragma unroll
            for (int g=0; g<2; g++){
                int k0 = 16*g + 2*m;
                #pragma unroll
                for (int q=0; q<2; q++){
                    int c = k0 + q*8;
                    float wa = w1s[c], wb = w1s[c+1], ba = b1s[c], bb = b1s[c+1];
                    I0[g][q*2]   = pack_hi(fmaxf(fmaf(x0,wa,ba),0.f), fmaxf(fmaf(x0,wb,bb),0.f));
                    I0[g][q*2+1] = pack_hi(fmaxf(fmaf(x1,wa,ba),0.f), fmaxf(fmaf(x1,wb,bb),0.f));
                    I1[g][q*2]   = pack_hi(fmaxf(fmaf(x2,wa,ba),0.f), fmaxf(fmaf(x2,wb,bb),0.f));
                    I1[g][q*2+1] = pack_hi(fmaxf(fmaf(x3,wa,ba),0.f), fmaxf(fmaf(x3,wb,bb),0.f));
                }
            }
        }

        const float* bias = smf + BIAS_F;
        layer_cv<2,8 >(sv+O2, bias+0,   I0, I1, P0, P1, lane);  // L2: 32->64
        layer_cv<4,8 >(sv+O3, bias+64,  P0, P1, Q0, Q1, lane);  // L3: 64->64
        layer_cv<4,8 >(sv+O4, bias+128, Q0, Q1, P0, P1, lane);  // L4: 64->64
        layer_cv<4,16>(sv+O5, bias+192, P0, P1, A0, A1, lane);  // L5: 64->128

        // --- layer6 (128->128): nf-quad streaming with fused segment reduction ---
        {
            const ulonglong2* S = sv+O6;
            const float* b6 = bias+320;
            int m2 = (lane&3)*2;
            #pragma unroll
            for (int nf0=0; nf0<16; nf0+=4){
                float Ca0[4],Cb0[4],Cc0[4],Cd0[4];
                float Ca1[4],Cb1[4],Cc1[4],Cd1[4];
                {
                    float2 ba = *(const float2*)(b6 + (nf0  )*8 + m2);
                    float2 bb = *(const float2*)(b6 + (nf0+1)*8 + m2);
                    float2 bc = *(const float2*)(b6 + (nf0+2)*8 + m2);
                    float2 bd = *(const float2*)(b6 + (nf0+3)*8 + m2);
                    Ca0[0]=ba.x;Ca0[1]=ba.y;Ca0[2]=ba.x;Ca0[3]=ba.y;
                    Ca1[0]=ba.x;Ca1[1]=ba.y;Ca1[2]=ba.x;Ca1[3]=ba.y;
                    Cb0[0]=bb.x;Cb0[1]=bb.y;Cb0[2]=bb.x;Cb0[3]=bb.y;
                    Cb1[0]=bb.x;Cb1[1]=bb.y;Cb1[2]=bb.x;Cb1[3]=bb.y;
                    Cc0[0]=bc.x;Cc0[1]=bc.y;Cc0[2]=bc.x;Cc0[3]=bc.y;
                    Cc1[0]=bc.x;Cc1[1]=bc.y;Cc1[2]=bc.x;Cc1[3]=bc.y;
                    Cd0[0]=bd.x;Cd0[1]=bd.y;Cd0[2]=bd.x;Cd0[3]=bd.y;
                    Cd1[0]=bd.x;Cd1[1]=bd.y;Cd1[2]=bd.x;Cd1[3]=bd.y;
                }
                #pragma unroll
                for (int kf=0;kf<8;kf++){
                    ulonglong2 fA = S[(kf*16+nf0  )*32+lane];
                    ulonglong2 fB = S[(kf*16+nf0+1)*32+lane];
                    ulonglong2 fC = S[(kf*16+nf0+2)*32+lane];
                    ulonglong2 fD = S[(kf*16+nf0+3)*32+lane];
                    MMA4(Ca0, A0[kf], fA.x); MMA4(Ca1, A1[kf], fA.x);
                    MMA4(Cb0, A0[kf], fB.x); MMA4(Cb1, A1[kf], fB.x);
                    MMA4(Cc0, A0[kf], fC.x); MMA4(Cc1, A1[kf], fC.x);
                    MMA4(Cd0, A0[kf], fD.x); MMA4(Cd1, A1[kf], fD.x);
                    MMA4(Ca0, A0[kf], fA.y); MMA4(Ca1, A1[kf], fA.y);
                    MMA4(Cb0, A0[kf], fB.y); MMA4(Cb1, A1[kf], fB.y);
                    MMA4(Cc0, A0[kf], fC.y); MMA4(Cc1, A1[kf], fC.y);
                    MMA4(Cd0, A0[kf], fD.y); MMA4(Cd1, A1[kf], fD.y);
                }
                reduce2(Ca0, Cb0, v0r, v1r, b0i, b1i, lane, m, nf0*8,      nf0==0);
                reduce2(Cc0, Cd0, v0r, v1r, b0i, b1i, lane, m, nf0*8+16,   false);
                reduce2(Ca1, Cb1, v2r, v3r, b2i, b3i, lane, m, nf0*8,      nf0==0);
                reduce2(Cc1, Cd1, v2r, v3r, b2i, b3i, lane, m, nf0*8+16,   false);
            }
        }
    }
}

// ================= graph-level MLP: warp per row =================
__global__ void __launch_bounds__(256,2)
graph_kernel(float* __restrict__ out)
{
    __shared__ float sF1[128*64];
    __shared__ float sFB1[64];
    __shared__ float sF2[64*32];
    __shared__ float sFB2[32];
    __shared__ float sF3[32*NCLS];
    __shared__ float sFB3[NCLS];
    __shared__ float sG0[128];

    int tid = threadIdx.x, lane = tid&31, w = tid>>5;
    for (int i=tid;i<128*64;i+=256) sF1[i]=d_F1[i];
    for (int i=tid;i<64;i+=256)     sFB1[i]=d_FB1[i];
    for (int i=tid;i<64*32;i+=256)  sF2[i]=d_F2[i];
    for (int i=tid;i<32;i+=256)     sFB2[i]=d_FB2[i];
    for (int i=tid;i<32*NCLS;i+=256) sF3[i]=d_F3[i];
    for (int i=tid;i<NCLS;i+=256)   sFB3[i]=d_FB3[i];
    for (int i=tid;i<128;i+=256)    sG0[i]=d_g0[i];
    __syncthreads();

    int row = blockIdx.x*8 + w;
    if (row >= BGR) return;

    float cnt = d_cnts[row];
    bool nz = cnt > 0.5f;
    float inv = nz ? 1.f/cnt : 0.f;

    float g[4];
    {
        float4 s4 = ((const float4*)(d_sums + (size_t)row*128))[lane];
        if (nz){ g[0]=s4.x*inv; g[1]=s4.y*inv; g[2]=s4.z*inv; g[3]=s4.w*inv; }
        else { float4 g4 = ((const float4*)sG0)[lane]; g[0]=g4.x; g[1]=g4.y; g[2]=g4.z; g[3]=g4.w; }
    }
    const unsigned FULL = 0xffffffffu;
    float za = sFB1[lane], zb = sFB1[lane+32];
    #pragma unroll
    for (int k4=0;k4<32;k4++){
        #pragma unroll
        for (int i=0;i<4;i++){
            float gk = __shfl_sync(FULL, g[i], k4);
            int k = k4*4+i;
            za = fmaf(gk, sF1[k*64+lane],    za);
            zb = fmaf(gk, sF1[k*64+lane+32], zb);
        }
    }
    float h1a = fmaxf(za,0.f), h1b = fmaxf(zb,0.f);
    float z2 = sFB2[lane];
    #pragma unroll
    for (int k=0;k<32;k++){
        float hk = __shfl_sync(FULL, h1a, k);
        z2 = fmaf(hk, sF2[k*32+lane], z2);
    }
    #pragma unroll
    for (int k=0;k<32;k++){
        float hk = __shfl_sync(FULL, h1b, k);
        z2 = fmaf(hk, sF2[(k+32)*32+lane], z2);
    }
    float h2 = fmaxf(z2,0.f);
    float o[NCLS];
    #pragma unroll
    for (int c=0;c<NCLS;c++) o[c] = h2 * sF3[lane*NCLS+c];
    #pragma unroll
    for (int c=0;c<NCLS;c++){
        o[c] += __shfl_xor_sync(FULL,o[c],16);
        o[c] += __shfl_xor_sync(FULL,o[c],8);
        o[c] += __shfl_xor_sync(FULL,o[c],4);
        o[c] += __shfl_xor_sync(FULL,o[c],2);
        o[c] += __shfl_xor_sync(FULL,o[c],1);
    }
    if (lane==0){
        #pragma unroll
        for (int c=0;c<NCLS;c++) out[row*NCLS+c] = o[c] + sFB3[c];
    }
}

// ================= launch =================
extern "C" void kernel_launch(void* const* d_in, const int* in_sizes, int n_in,
                              void* d_out, int out_size)
{
    const float* x     = (const float*)d_in[0];
    const int*   batch = (const int*)d_in[1];
    int n = in_sizes[0];

    cudaFuncSetAttribute(node_kernel, cudaFuncAttributeMaxDynamicSharedMemorySize, NODE_SMEM_BYTES);

    prep_kernel<<<1,256>>>(
        (const float*)d_in[3],  (const float*)d_in[4],  (const float*)d_in[5],
        (const float*)d_in[6],  (const float*)d_in[7],  (const float*)d_in[8],
        (const float*)d_in[9],  (const float*)d_in[10],
        (const float*)d_in[11], (const float*)d_in[12], (const float*)d_in[13],
        (const float*)d_in[14], (const float*)d_in[15],
        (const float*)d_in[16], (const float*)d_in[17], (const float*)d_in[18],
        (const float*)d_in[19], (const float*)d_in[20], (const float*)d_in[21],
        (const float*)d_in[22], (const float*)d_in[23], (const float*)d_in[24],
        (const float*)d_in[25], (const float*)d_in[26]);
    pack_kernel<<<1,256>>>();
    zero_kernel<<<(BGR*128 + 255)/256, 256>>>();
    node_kernel<<<148, NTHR, NODE_SMEM_BYTES>>>(x, batch, n);
    graph_kernel<<<BGR/8, 256>>>((float*)d_out);
}

// round 12
// speedup vs baseline: 1.4211x; 1.4211x over previous
#include <cuda_runtime.h>
#include <cuda_bf16.h>
#include <cstdint>

#define EPSV 1e-5f
#define BGR 4096
#define NCLS 7
#define NTHR 384
typedef unsigned long long u64;
typedef unsigned int u32;

// ================= device globals =================
__device__ float d_w1[32], d_b1[32];
__device__ float d_W2[32*64],   d_B2[64];
__device__ float d_W3[64*64],   d_B3[64];
__device__ float d_W4[64*64],   d_B4[64];
__device__ float d_W5T[128*64], d_B5[128];   // [out(128)][in(64)]
__device__ float d_W6[128*128], d_B6[128];
__device__ float d_F1[128*64],  d_FB1[64];
__device__ float d_F2[64*32],   d_FB2[32];
__device__ float d_F3[32*NCLS], d_FB3[NCLS];
__device__ float d_g0[128];
__device__ float d_sums[BGR*128];
__device__ float d_cnts[BGR];

// interleaved fragment streams: per (kf,nf,lane) one ulonglong2 = {hi_frag, lo_frag}
__device__ ulonglong2 g_S2[512];    // K=32 (KF=2),  N=64 (NF=8)
__device__ ulonglong2 g_S3[1024];   // K=64, N=64
__device__ ulonglong2 g_S4[1024];   // K=64, N=64
__device__ ulonglong2 g_S5[2048];   // K=64, N=128
__device__ ulonglong2 g_S6[4096];   // K=128, N=128

__device__ __forceinline__ float bn_a(const float* bn, int c, int i){ return bn[0*c+i]*rsqrtf(bn[3*c+i]+EPSV); }
__device__ __forceinline__ float bn_c(const float* bn, int c, int i, float a){ return bn[1*c+i]-bn[2*c+i]*a; }

// ================= prep: fold BNs (fp32, validated) =================
__global__ void prep_kernel(
    const float* w1, const float* b1, const float* bn1,
    const float* w2, const float* b2, const float* bn2,
    const float* c1aw, const float* c1ab,
    const float* c1bw, const float* c1bb, const float* cbn1,
    const float* c2aw, const float* c2ab,
    const float* c2bw, const float* c2bb, const float* cbn2,
    const float* f1w, const float* f1b, const float* fbn1,
    const float* f2w, const float* f2b, const float* fbn2,
    const float* f3w, const float* f3b)
{
    int t = threadIdx.x;
    for (int i=t;i<32;i+=256){ d_w1[i]=w1[i]; d_b1[i]=b1[i]; }
    for (int i=t;i<32*64;i+=256){ int k=i>>6; d_W2[i]=bn_a(bn1,32,k)*w2[i]; }
    for (int j=t;j<64;j+=256){ float s=b2[j];
        for(int k=0;k<32;k++){float a=bn_a(bn1,32,k); s+=bn_c(bn1,32,k,a)*w2[k*64+j];}
        d_B2[j]=s; }
    for (int i=t;i<64*64;i+=256){ int k=i>>6; d_W3[i]=bn_a(bn2,64,k)*c1aw[i]; }
    for (int j=t;j<64;j+=256){ float s=c1ab[j];
        for(int k=0;k<64;k++){float a=bn_a(bn2,64,k); s+=bn_c(bn2,64,k,a)*c1aw[k*64+j];}
        d_B3[j]=s; }
    for (int i=t;i<64*64;i+=256) d_W4[i]=c1bw[i];
    for (int j=t;j<64;j+=256)    d_B4[j]=c1bb[j];
    for (int i=t;i<128*64;i+=256){ int k=i>>6, m=i&63; d_W5T[i]=bn_a(cbn1,64,m)*c2aw[m*128+k]; }
    for (int k=t;k<128;k+=256){ float s=c2ab[k];
        for(int m=0;m<64;m++){float a=bn_a(cbn1,64,m); s+=bn_c(cbn1,64,m,a)*c2aw[m*128+k];}
        d_B5[k]=s; }
    for (int i=t;i<128*128;i+=256) d_W6[i]=c2bw[i];
    for (int j=t;j<128;j+=256)     d_B6[j]=c2bb[j];
    for (int i=t;i<128*64;i+=256){ int k=i>>6; d_F1[i]=bn_a(cbn2,128,k)*f1w[i]; }
    for (int j=t;j<64;j+=256){ float s=f1b[j];
        for(int k=0;k<128;k++){float a=bn_a(cbn2,128,k); s+=bn_c(cbn2,128,k,a)*f1w[k*64+j];}
        d_FB1[j]=s; }
    for (int k=t;k<128;k+=256){ float a=bn_a(cbn2,128,k); d_g0[k]=-bn_c(cbn2,128,k,a)/a; }
    for (int i=t;i<64*32;i+=256){ int k=i>>5; d_F2[i]=bn_a(fbn1,64,k)*f2w[i]; }
    for (int j=t;j<32;j+=256){ float s=f2b[j];
        for(int k=0;k<64;k++){float a=bn_a(fbn1,64,k); s+=bn_c(fbn1,64,k,a)*f2w[k*32+j];}
        d_FB2[j]=s; }
    for (int i=t;i<32*NCLS;i+=256){ int k=i/NCLS; d_F3[i]=bn_a(fbn2,32,k)*f3w[i]; }
    for (int j=t;j<NCLS;j+=256){ float s=f3b[j];
        for(int k=0;k<32;k++){float a=bn_a(fbn2,32,k); s+=bn_c(fbn2,32,k,a)*f3w[k*NCLS+j];}
        d_FB3[j]=s; }
}

// ================= pack helper =================
__device__ __forceinline__ u32 pkbf(float a, float b){
    __nv_bfloat16 ha=__float2bfloat16(a), hb=__float2bfloat16(b);
    return (u32)__bfloat16_as_ushort(ha) | ((u32)__bfloat16_as_ushort(hb)<<16);
}
__device__ void pack_stream(ulonglong2* S, const float* W, int KF, int NF, int N,
                            bool tr, int ld, int tid, int nthr)
{
    int tot = KF*NF*32;
    for (int i=tid;i<tot;i+=nthr){
        int lane = i&31, nf=(i>>5)%NF, kf=i/(32*NF);
        int nn = nf*8 + (lane>>2);
        int k0 = kf*16 + (lane&3)*2;
        float v[4];
        int ks[4]={k0,k0+1,k0+8,k0+9};
        #pragma unroll
        for (int j=0;j<4;j++) v[j] = tr ? W[nn*ld + ks[j]] : W[ks[j]*N + nn];
        u32 h0 = pkbf(v[0],v[1]), h1 = pkbf(v[2],v[3]);
        float l[4];
        #pragma unroll
        for (int j=0;j<4;j++) l[j] = v[j] - __bfloat162float(__float2bfloat16(v[j]));
        u32 L0 = pkbf(l[0],l[1]), L1 = pkbf(l[2],l[3]);
        ulonglong2 e;
        e.x = (u64)h0 | ((u64)h1<<32);
        e.y = (u64)L0 | ((u64)L1<<32);
        S[(kf*NF+nf)*32+lane] = e;
    }
}

// merged: all blocks zero their slice; last block also packs all streams
__global__ void packzero_kernel(){
    int i = blockIdx.x*blockDim.x + threadIdx.x;
    if (i < BGR*128) d_sums[i] = 0.f;
    if (i < BGR)     d_cnts[i] = 0.f;
    if (blockIdx.x == gridDim.x-1){
        int t = threadIdx.x;
        pack_stream(g_S2, d_W2,  2, 8,  64, false, 0,  t,256);
        pack_stream(g_S3, d_W3,  4, 8,  64, false, 0,  t,256);
        pack_stream(g_S4, d_W4,  4, 8,  64, false, 0,  t,256);
        pack_stream(g_S5, d_W5T, 4,16, 128, true, 64,  t,256);
        pack_stream(g_S6, d_W6,  8,16, 128, false, 0,  t,256);
    }
}

// ================= node kernel (exact R9 champion) =================
#define O2 0
#define O3 512
#define O4 1536
#define O5 2560
#define O6 4608
#define SMV 8704
#define BIAS_F (SMV*4)
#define W1_F   (BIAS_F+448)
#define NODE_SMEM_BYTES ((W1_F+64)*4)

__device__ __forceinline__ void mma_bf16(float& c0,float& c1,float& c2,float& c3,
                                         u32 a0,u32 a1,u32 a2,u32 a3, u32 b0, u32 b1){
    asm volatile("mma.sync.aligned.m16n8k16.row.col.f32.bf16.bf16.f32 "
        "{%0,%1,%2,%3},{%4,%5,%6,%7},{%8,%9},{%0,%1,%2,%3};"
        : "+f"(c0),"+f"(c1),"+f"(c2),"+f"(c3)
        : "r"(a0),"r"(a1),"r"(a2),"r"(a3),"r"(b0),"r"(b1));
}
__device__ __forceinline__ u32 pack_hi(float v0, float v1){
    return (u32)__bfloat16_as_ushort(__float2bfloat16(v0))
         | ((u32)__bfloat16_as_ushort(__float2bfloat16(v1))<<16);
}

template<int KF,int NF>
__device__ __forceinline__ void run_layer(const ulonglong2* __restrict__ S,
    const float* __restrict__ bias, const u32 Ah[][4], float C[][4], int lane)
{
    int m2 = (lane&3)*2;
    #pragma unroll
    for (int nf=0;nf<NF;nf++){
        float2 bv = *(const float2*)(bias + nf*8 + m2);
        C[nf][0]=bv.x; C[nf][1]=bv.y; C[nf][2]=bv.x; C[nf][3]=bv.y;
    }
    #pragma unroll
    for (int kf=0;kf<KF;kf++){
        #pragma unroll
        for (int nf0=0;nf0<NF;nf0+=4){
            ulonglong2 f[4];
            #pragma unroll
            for (int j=0;j<4;j++) f[j] = S[(kf*NF+nf0+j)*32+lane];
            #pragma unroll
            for (int j=0;j<4;j++){
                int nf=nf0+j;
                mma_bf16(C[nf][0],C[nf][1],C[nf][2],C[nf][3],
                         Ah[kf][0],Ah[kf][1],Ah[kf][2],Ah[kf][3],
                         (u32)f[j].x,(u32)(f[j].x>>32));
            }
            #pragma unroll
            for (int j=0;j<4;j++){
                int nf=nf0+j;
                mma_bf16(C[nf][0],C[nf][1],C[nf][2],C[nf][3],
                         Ah[kf][0],Ah[kf][1],Ah[kf][2],Ah[kf][3],
                         (u32)f[j].y,(u32)(f[j].y>>32));
            }
        }
    }
}

template<int NF>
__device__ __forceinline__ void conv_act(const float C[][4], u32 Ah[][4]){
    #pragma unroll
    for (int g=0;g<NF/2;g++){
        #pragma unroll
        for (int h=0;h<2;h++){
            float v0 = fmaxf(C[2*g][2*h],0.f),   v1 = fmaxf(C[2*g][2*h+1],0.f);
            float w0 = fmaxf(C[2*g+1][2*h],0.f), w1 = fmaxf(C[2*g+1][2*h+1],0.f);
            Ah[g][h]   = pack_hi(v0,v1);
            Ah[g][2+h] = pack_hi(w0,w1);
        }
    }
}

__global__ void __launch_bounds__(NTHR,1)
node_kernel(const float* __restrict__ x, const int* __restrict__ batch, int n)
{
    extern __shared__ float smf[];
    ulonglong2* sv = (ulonglong2*)smf;
    int tid = threadIdx.x;
    int lane = tid & 31, w = tid >> 5;

    for (int i=tid;i<512;i+=NTHR)  sv[O2+i]=g_S2[i];
    for (int i=tid;i<1024;i+=NTHR){ sv[O3+i]=g_S3[i]; sv[O4+i]=g_S4[i]; }
    for (int i=tid;i<2048;i+=NTHR) sv[O5+i]=g_S5[i];
    for (int i=tid;i<4096;i+=NTHR) sv[O6+i]=g_S6[i];
    { float* bias = smf + BIAS_F;
      for (int i=tid;i<64;i+=NTHR){ bias[i]=d_B2[i]; bias[64+i]=d_B3[i]; bias[128+i]=d_B4[i]; }
      for (int i=tid;i<128;i+=NTHR){ bias[192+i]=d_B5[i]; bias[320+i]=d_B6[i]; }
      float* w1s = smf + W1_F;
      for (int i=tid;i<32;i+=NTHR){ w1s[i]=d_w1[i]; w1s[32+i]=d_b1[i]; } }
    __syncthreads();

    const unsigned FULL = 0xffffffffu;
    int r = lane>>2, m = lane&3;

    const int ntasks = (n + 15) >> 4;
    const int nwarps = gridDim.x * (NTHR/32);
    int gw = blockIdx.x * (NTHR/32) + w;

    for (int task = gw; task < ntasks; task += nwarps){
        int e0 = task*16 + r, e1 = e0 + 8;
        bool v0r = e0 < n, v1r = e1 < n;
        float x0 = v0r ? x[e0] : 0.f;
        float x1 = v1r ? x[e1] : 0.f;
        int b0i = v0r ? batch[e0] : -1;
        int b1i = v1r ? batch[e1] : -1;

        u32 Ah[8][4];
        float C[16][4];

        {
            const float* w1s = smf + W1_F;
            const float* b1s = w1s + 32;
            #pragma unroll
            for (int g=0; g<2; g++){
                int k0 = 16*g + 2*m;
                #pragma unroll
                for (int q=0; q<2; q++){
                    int c = k0 + q*8;
                    float wa = w1s[c], wb = w1s[c+1], ba = b1s[c], bb = b1s[c+1];
                    float p00 = fmaxf(fmaf(x0,wa,ba),0.f), p01 = fmaxf(fmaf(x0,wb,bb),0.f);
                    float p10 = fmaxf(fmaf(x1,wa,ba),0.f), p11 = fmaxf(fmaf(x1,wb,bb),0.f);
                    Ah[g][q*2]   = pack_hi(p00,p01);
                    Ah[g][q*2+1] = pack_hi(p10,p11);
                }
            }
        }

        const float* bias = smf + BIAS_F;
        run_layer<2,8 >(sv+O2, bias+0,   Ah, C, lane);
        conv_act<8>(C, Ah);
        run_layer<4,8 >(sv+O3, bias+64,  Ah, C, lane);
        conv_act<8>(C, Ah);
        run_layer<4,8 >(sv+O4, bias+128, Ah, C, lane);
        conv_act<8>(C, Ah);
        run_layer<4,16>(sv+O5, bias+192, Ah, C, lane);
        conv_act<16>(C, Ah);
        run_layer<8,16>(sv+O6, bias+320, Ah, C, lane);

        bool uni = __all_sync(FULL, v0r && v1r);
        int bf_ = __shfl_sync(FULL, b0i, 0);
        uni = uni && __all_sync(FULL, (b0i==bf_) && (b1i==bf_));
        if (uni){
            float* dst = d_sums + (size_t)bf_*128;
            #pragma unroll
            for (int f=0; f<16; f++){
                float s0 = fmaxf(C[f][0],0.f) + fmaxf(C[f][2],0.f);
                float s1 = fmaxf(C[f][1],0.f) + fmaxf(C[f][3],0.f);
                s0 += __shfl_xor_sync(FULL,s0,4);  s1 += __shfl_xor_sync(FULL,s1,4);
                s0 += __shfl_xor_sync(FULL,s0,8);  s1 += __shfl_xor_sync(FULL,s1,8);
                s0 += __shfl_xor_sync(FULL,s0,16); s1 += __shfl_xor_sync(FULL,s1,16);
                if (lane < 4){
                    atomicAdd(dst + f*8 + 2*lane,     s0);
                    atomicAdd(dst + f*8 + 2*lane + 1, s1);
                }
            }
            if (lane==0) atomicAdd(&d_cnts[bf_], 16.f);
        } else {
            unsigned vb0 = __ballot_sync(FULL, v0r && m==0);
            unsigned vb1 = __ballot_sync(FULL, v1r && m==0);
            unsigned rem = 0;
            #pragma unroll
            for (int rr=0; rr<8; rr++){
                if ((vb0>>(4*rr))&1) rem |= 1u<<rr;
                if ((vb1>>(4*rr))&1) rem |= 1u<<(rr+8);
            }
            while (rem){
                int j = __ffs(rem)-1;
                int bt = (j<8) ? __shfl_sync(FULL,b0i,j*4) : __shfl_sync(FULL,b1i,(j-8)*4);
                bool p0 = (b0i==bt), p1 = (b1i==bt);
                float* dst = d_sums + (size_t)bt*128;
                #pragma unroll
                for (int f=0; f<16; f++){
                    float s0 = (p0?fmaxf(C[f][0],0.f):0.f) + (p1?fmaxf(C[f][2],0.f):0.f);
                    float s1 = (p0?fmaxf(C[f][1],0.f):0.f) + (p1?fmaxf(C[f][3],0.f):0.f);
                    s0 += __shfl_xor_sync(FULL,s0,4);  s1 += __shfl_xor_sync(FULL,s1,4);
                    s0 += __shfl_xor_sync(FULL,s0,8);  s1 += __shfl_xor_sync(FULL,s1,8);
                    s0 += __shfl_xor_sync(FULL,s0,16); s1 += __shfl_xor_sync(FULL,s1,16);
                    if (lane < 4){
                        atomicAdd(dst + f*8 + 2*lane,     s0);
                        atomicAdd(dst + f*8 + 2*lane + 1, s1);
                    }
                }
                unsigned m0 = __ballot_sync(FULL, p0 && m==0);
                unsigned m1 = __ballot_sync(FULL, p1 && m==0);
                if (lane==0) atomicAdd(&d_cnts[bt], (float)(__popc(m0)+__popc(m1)));
                unsigned clr = 0;
                #pragma unroll
                for (int rr=0; rr<8; rr++){
                    if ((m0>>(4*rr))&1) clr |= 1u<<rr;
                    if ((m1>>(4*rr))&1) clr |= 1u<<(rr+8);
                }
                rem &= ~clr;
            }
        }
    }
}

// ================= graph-level MLP: persistent, warp per row =================
__global__ void __launch_bounds__(256,2)
graph_kernel(float* __restrict__ out)
{
    __shared__ float sF1[128*64];
    __shared__ float sFB1[64];
    __shared__ float sF2[64*32];
    __shared__ float sFB2[32];
    __shared__ float sF3[32*NCLS];
    __shared__ float sFB3[NCLS];
    __shared__ float sG0[128];

    int tid = threadIdx.x, lane = tid&31, w = tid>>5;
    for (int i=tid;i<128*64;i+=256) sF1[i]=d_F1[i];
    for (int i=tid;i<64;i+=256)     sFB1[i]=d_FB1[i];
    for (int i=tid;i<64*32;i+=256)  sF2[i]=d_F2[i];
    for (int i=tid;i<32;i+=256)     sFB2[i]=d_FB2[i];
    for (int i=tid;i<32*NCLS;i+=256) sF3[i]=d_F3[i];
    for (int i=tid;i<NCLS;i+=256)   sFB3[i]=d_FB3[i];
    for (int i=tid;i<128;i+=256)    sG0[i]=d_g0[i];
    __syncthreads();

    const unsigned FULL = 0xffffffffu;
    for (int row = blockIdx.x*8 + w; row < BGR; row += gridDim.x*8){
        float cnt = d_cnts[row];
        bool nz = cnt > 0.5f;
        float inv = nz ? 1.f/cnt : 0.f;

        float g[4];
        {
            float4 s4 = ((const float4*)(d_sums + (size_t)row*128))[lane];
            if (nz){ g[0]=s4.x*inv; g[1]=s4.y*inv; g[2]=s4.z*inv; g[3]=s4.w*inv; }
            else { float4 g4 = ((const float4*)sG0)[lane]; g[0]=g4.x; g[1]=g4.y; g[2]=g4.z; g[3]=g4.w; }
        }
        float za = sFB1[lane], zb = sFB1[lane+32];
        #pragma unroll
        for (int k4=0;k4<32;k4++){
            #pragma unroll
            for (int i=0;i<4;i++){
                float gk = __shfl_sync(FULL, g[i], k4);
                int k = k4*4+i;
                za = fmaf(gk, sF1[k*64+lane],    za);
                zb = fmaf(gk, sF1[k*64+lane+32], zb);
            }
        }
        float h1a = fmaxf(za,0.f), h1b = fmaxf(zb,0.f);
        float z2 = sFB2[lane];
        #pragma unroll
        for (int k=0;k<32;k++){
            float hk = __shfl_sync(FULL, h1a, k);
            z2 = fmaf(hk, sF2[k*32+lane], z2);
        }
        #pragma unroll
        for (int k=0;k<32;k++){
            float hk = __shfl_sync(FULL, h1b, k);
            z2 = fmaf(hk, sF2[(k+32)*32+lane], z2);
        }
        float h2 = fmaxf(z2,0.f);
        float o[NCLS];
        #pragma unroll
        for (int c=0;c<NCLS;c++) o[c] = h2 * sF3[lane*NCLS+c];
        #pragma unroll
        for (int c=0;c<NCLS;c++){
            o[c] += __shfl_xor_sync(FULL,o[c],16);
            o[c] += __shfl_xor_sync(FULL,o[c],8);
            o[c] += __shfl_xor_sync(FULL,o[c],4);
            o[c] += __shfl_xor_sync(FULL,o[c],2);
            o[c] += __shfl_xor_sync(FULL,o[c],1);
        }
        if (lane==0){
            #pragma unroll
            for (int c=0;c<NCLS;c++) out[row*NCLS+c] = o[c] + sFB3[c];
        }
    }
}

// ================= launch =================
extern "C" void kernel_launch(void* const* d_in, const int* in_sizes, int n_in,
                              void* d_out, int out_size)
{
    const float* x     = (const float*)d_in[0];
    const int*   batch = (const int*)d_in[1];
    int n = in_sizes[0];

    cudaFuncSetAttribute(node_kernel, cudaFuncAttributeMaxDynamicSharedMemorySize, NODE_SMEM_BYTES);

    prep_kernel<<<1,256>>>(
        (const float*)d_in[3],  (const float*)d_in[4],  (const float*)d_in[5],
        (const float*)d_in[6],  (const float*)d_in[7],  (const float*)d_in[8],
        (const float*)d_in[9],  (const float*)d_in[10],
        (const float*)d_in[11], (const float*)d_in[12], (const float*)d_in[13],
        (const float*)d_in[14], (const float*)d_in[15],
        (const float*)d_in[16], (const float*)d_in[17], (const float*)d_in[18],
        (const float*)d_in[19], (const float*)d_in[20], (const float*)d_in[21],
        (const float*)d_in[22], (const float*)d_in[23], (const float*)d_in[24],
        (const float*)d_in[25], (const float*)d_in[26]);
    packzero_kernel<<<(BGR*128 + 255)/256, 256>>>();
    node_kernel<<<148, NTHR, NODE_SMEM_BYTES>>>(x, batch, n);
    graph_kernel<<<128, 256>>>((float*)d_out);
}

// round 15
// speedup vs baseline: 1.4465x; 1.0179x over previous
#include <cuda_runtime.h>
#include <cuda_bf16.h>
#include <cstdint>

#define EPSV 1e-5f
#define BGR 4096
#define NCLS 7
#define NTHR 384
typedef unsigned long long u64;
typedef unsigned int u32;

// ================= device globals =================
__device__ float d_w1[32], d_b1[32];
__device__ float d_W2[32*64],   d_B2[64];
__device__ float d_W3[64*64],   d_B3[64];
__device__ float d_W4[64*64],   d_B4[64];
__device__ float d_W5T[128*64], d_B5[128];   // [out(128)][in(64)]
__device__ float d_W6[128*128], d_B6[128];
__device__ float d_F1[128*64],  d_FB1[64];
__device__ float d_F2[64*32],   d_FB2[32];
__device__ float d_F3[32*NCLS], d_FB3[NCLS];
__device__ float d_g0[128];
__device__ float d_sums[BGR*128];
__device__ float d_cnts[BGR];

// interleaved fragment streams: per (kf,nf,lane) one ulonglong2 = {hi_frag, lo_frag}
__device__ ulonglong2 g_S2[512];    // K=32 (KF=2),  N=64 (NF=8)
__device__ ulonglong2 g_S3[1024];   // K=64, N=64
__device__ ulonglong2 g_S4[1024];   // K=64, N=64
__device__ ulonglong2 g_S5[2048];   // K=64, N=128
__device__ ulonglong2 g_S6[4096];   // K=128, N=128

__device__ __forceinline__ float bn_a(const float* bn, int c, int i){ return bn[0*c+i]*rsqrtf(bn[3*c+i]+EPSV); }
__device__ __forceinline__ float bn_c(const float* bn, int c, int i, float a){ return bn[1*c+i]-bn[2*c+i]*a; }

// ================= prep: fold BNs (fp32, validated) =================
__global__ void prep_kernel(
    const float* w1, const float* b1, const float* bn1,
    const float* w2, const float* b2, const float* bn2,
    const float* c1aw, const float* c1ab,
    const float* c1bw, const float* c1bb, const float* cbn1,
    const float* c2aw, const float* c2ab,
    const float* c2bw, const float* c2bb, const float* cbn2,
    const float* f1w, const float* f1b, const float* fbn1,
    const float* f2w, const float* f2b, const float* fbn2,
    const float* f3w, const float* f3b)
{
    int t = threadIdx.x;
    for (int i=t;i<32;i+=256){ d_w1[i]=w1[i]; d_b1[i]=b1[i]; }
    for (int i=t;i<32*64;i+=256){ int k=i>>6; d_W2[i]=bn_a(bn1,32,k)*w2[i]; }
    for (int j=t;j<64;j+=256){ float s=b2[j];
        for(int k=0;k<32;k++){float a=bn_a(bn1,32,k); s+=bn_c(bn1,32,k,a)*w2[k*64+j];}
        d_B2[j]=s; }
    for (int i=t;i<64*64;i+=256){ int k=i>>6; d_W3[i]=bn_a(bn2,64,k)*c1aw[i]; }
    for (int j=t;j<64;j+=256){ float s=c1ab[j];
        for(int k=0;k<64;k++){float a=bn_a(bn2,64,k); s+=bn_c(bn2,64,k,a)*c1aw[k*64+j];}
        d_B3[j]=s; }
    for (int i=t;i<64*64;i+=256) d_W4[i]=c1bw[i];
    for (int j=t;j<64;j+=256)    d_B4[j]=c1bb[j];
    for (int i=t;i<128*64;i+=256){ int k=i>>6, m=i&63; d_W5T[i]=bn_a(cbn1,64,m)*c2aw[m*128+k]; }
    for (int k=t;k<128;k+=256){ float s=c2ab[k];
        for(int m=0;m<64;m++){float a=bn_a(cbn1,64,m); s+=bn_c(cbn1,64,m,a)*c2aw[m*128+k];}
        d_B5[k]=s; }
    for (int i=t;i<128*128;i+=256) d_W6[i]=c2bw[i];
    for (int j=t;j<128;j+=256)     d_B6[j]=c2bb[j];
    for (int i=t;i<128*64;i+=256){ int k=i>>6; d_F1[i]=bn_a(cbn2,128,k)*f1w[i]; }
    for (int j=t;j<64;j+=256){ float s=f1b[j];
        for(int k=0;k<128;k++){float a=bn_a(cbn2,128,k); s+=bn_c(cbn2,128,k,a)*f1w[k*64+j];}
        d_FB1[j]=s; }
    for (int k=t;k<128;k+=256){ float a=bn_a(cbn2,128,k); d_g0[k]=-bn_c(cbn2,128,k,a)/a; }
    for (int i=t;i<64*32;i+=256){ int k=i>>5; d_F2[i]=bn_a(fbn1,64,k)*f2w[i]; }
    for (int j=t;j<32;j+=256){ float s=f2b[j];
        for(int k=0;k<64;k++){float a=bn_a(fbn1,64,k); s+=bn_c(fbn1,64,k,a)*f2w[k*32+j];}
        d_FB2[j]=s; }
    for (int i=t;i<32*NCLS;i+=256){ int k=i/NCLS; d_F3[i]=bn_a(fbn2,32,k)*f3w[i]; }
    for (int j=t;j<NCLS;j+=256){ float s=f3b[j];
        for(int k=0;k<32;k++){float a=bn_a(fbn2,32,k); s+=bn_c(fbn2,32,k,a)*f3w[k*NCLS+j];}
        d_FB3[j]=s; }
}

// ================= pack: weights -> interleaved hi/lo B-fragment streams =================
__device__ __forceinline__ u32 pkbf(float a, float b){
    __nv_bfloat16 ha=__float2bfloat16(a), hb=__float2bfloat16(b);
    return (u32)__bfloat16_as_ushort(ha) | ((u32)__bfloat16_as_ushort(hb)<<16);
}
__device__ void pack_stream(ulonglong2* S, const float* W, int KF, int NF, int N,
                            bool tr, int ld, int tid, int nthr)
{
    int tot = KF*NF*32;
    for (int i=tid;i<tot;i+=nthr){
        int lane = i&31, nf=(i>>5)%NF, kf=i/(32*NF);
        int nn = nf*8 + (lane>>2);
        int k0 = kf*16 + (lane&3)*2;
        float v[4];
        int ks[4]={k0,k0+1,k0+8,k0+9};
        #pragma unroll
        for (int j=0;j<4;j++) v[j] = tr ? W[nn*ld + ks[j]] : W[ks[j]*N + nn];
        u32 h0 = pkbf(v[0],v[1]), h1 = pkbf(v[2],v[3]);
        float l[4];
        #pragma unroll
        for (int j=0;j<4;j++) l[j] = v[j] - __bfloat162float(__float2bfloat16(v[j]));
        u32 L0 = pkbf(l[0],l[1]), L1 = pkbf(l[2],l[3]);
        ulonglong2 e;
        e.x = (u64)h0 | ((u64)h1<<32);
        e.y = (u64)L0 | ((u64)L1<<32);
        S[(kf*NF+nf)*32+lane] = e;
    }
}
__global__ void pack_kernel(){
    int t = threadIdx.x;
    pack_stream(g_S2, d_W2,  2, 8,  64, false, 0,  t,256);
    pack_stream(g_S3, d_W3,  4, 8,  64, false, 0,  t,256);
    pack_stream(g_S4, d_W4,  4, 8,  64, false, 0,  t,256);
    pack_stream(g_S5, d_W5T, 4,16, 128, true, 64,  t,256);
    pack_stream(g_S6, d_W6,  8,16, 128, false, 0,  t,256);
}

__global__ void zero_kernel(){
    int i = blockIdx.x*blockDim.x + threadIdx.x;
    if (i < BGR*128) d_sums[i] = 0.f;
    if (i < BGR)     d_cnts[i] = 0.f;
}

// ================= node kernel (R9 champion, verbatim) =================
#define O2 0
#define O3 512
#define O4 1536
#define O5 2560
#define O6 4608
#define SMV 8704
#define BIAS_F (SMV*4)
#define W1_F   (BIAS_F+448)
#define NODE_SMEM_BYTES ((W1_F+64)*4)

__device__ __forceinline__ void mma_bf16(float& c0,float& c1,float& c2,float& c3,
                                         u32 a0,u32 a1,u32 a2,u32 a3, u32 b0, u32 b1){
    asm volatile("mma.sync.aligned.m16n8k16.row.col.f32.bf16.bf16.f32 "
        "{%0,%1,%2,%3},{%4,%5,%6,%7},{%8,%9},{%0,%1,%2,%3};"
        : "+f"(c0),"+f"(c1),"+f"(c2),"+f"(c3)
        : "r"(a0),"r"(a1),"r"(a2),"r"(a3),"r"(b0),"r"(b1));
}
__device__ __forceinline__ u32 pack_hi(float v0, float v1){
    return (u32)__bfloat16_as_ushort(__float2bfloat16(v0))
         | ((u32)__bfloat16_as_ushort(__float2bfloat16(v1))<<16);
}

template<int KF,int NF>
__device__ __forceinline__ void run_layer(const ulonglong2* __restrict__ S,
    const float* __restrict__ bias, const u32 Ah[][4], float C[][4], int lane)
{
    int m2 = (lane&3)*2;
    #pragma unroll
    for (int nf=0;nf<NF;nf++){
        float2 bv = *(const float2*)(bias + nf*8 + m2);
        C[nf][0]=bv.x; C[nf][1]=bv.y; C[nf][2]=bv.x; C[nf][3]=bv.y;
    }
    #pragma unroll
    for (int kf=0;kf<KF;kf++){
        #pragma unroll
        for (int nf0=0;nf0<NF;nf0+=4){
            ulonglong2 f[4];
            #pragma unroll
            for (int j=0;j<4;j++) f[j] = S[(kf*NF+nf0+j)*32+lane];
            #pragma unroll
            for (int j=0;j<4;j++){
                int nf=nf0+j;
                mma_bf16(C[nf][0],C[nf][1],C[nf][2],C[nf][3],
                         Ah[kf][0],Ah[kf][1],Ah[kf][2],Ah[kf][3],
                         (u32)f[j].x,(u32)(f[j].x>>32));
            }
            #pragma unroll
            for (int j=0;j<4;j++){
                int nf=nf0+j;
                mma_bf16(C[nf][0],C[nf][1],C[nf][2],C[nf][3],
                         Ah[kf][0],Ah[kf][1],Ah[kf][2],Ah[kf][3],
                         (u32)f[j].y,(u32)(f[j].y>>32));
            }
        }
    }
}

template<int NF>
__device__ __forceinline__ void conv_act(const float C[][4], u32 Ah[][4]){
    #pragma unroll
    for (int g=0;g<NF/2;g++){
        #pragma unroll
        for (int h=0;h<2;h++){
            float v0 = fmaxf(C[2*g][2*h],0.f),   v1 = fmaxf(C[2*g][2*h+1],0.f);
            float w0 = fmaxf(C[2*g+1][2*h],0.f), w1 = fmaxf(C[2*g+1][2*h+1],0.f);
            Ah[g][h]   = pack_hi(v0,v1);
            Ah[g][2+h] = pack_hi(w0,w1);
        }
    }
}

__global__ void __launch_bounds__(NTHR,1)
node_kernel(const float* __restrict__ x, const int* __restrict__ batch, int n)
{
    extern __shared__ float smf[];
    ulonglong2* sv = (ulonglong2*)smf;
    int tid = threadIdx.x;
    int lane = tid & 31, w = tid >> 5;

    for (int i=tid;i<512;i+=NTHR)  sv[O2+i]=g_S2[i];
    for (int i=tid;i<1024;i+=NTHR){ sv[O3+i]=g_S3[i]; sv[O4+i]=g_S4[i]; }
    for (int i=tid;i<2048;i+=NTHR) sv[O5+i]=g_S5[i];
    for (int i=tid;i<4096;i+=NTHR) sv[O6+i]=g_S6[i];
    { float* bias = smf + BIAS_F;
      for (int i=tid;i<64;i+=NTHR){ bias[i]=d_B2[i]; bias[64+i]=d_B3[i]; bias[128+i]=d_B4[i]; }
      for (int i=tid;i<128;i+=NTHR){ bias[192+i]=d_B5[i]; bias[320+i]=d_B6[i]; }
      float* w1s = smf + W1_F;
      for (int i=tid;i<32;i+=NTHR){ w1s[i]=d_w1[i]; w1s[32+i]=d_b1[i]; } }
    __syncthreads();

    const unsigned FULL = 0xffffffffu;
    int r = lane>>2, m = lane&3;

    const int ntasks = (n + 15) >> 4;
    const int nwarps = gridDim.x * (NTHR/32);
    int gw = blockIdx.x * (NTHR/32) + w;

    for (int task = gw; task < ntasks; task += nwarps){
        int e0 = task*16 + r, e1 = e0 + 8;
        bool v0r = e0 < n, v1r = e1 < n;
        float x0 = v0r ? x[e0] : 0.f;
        float x1 = v1r ? x[e1] : 0.f;
        int b0i = v0r ? batch[e0] : -1;
        int b1i = v1r ? batch[e1] : -1;

        u32 Ah[8][4];
        float C[16][4];

        {
            const float* w1s = smf + W1_F;
            const float* b1s = w1s + 32;
            #pragma unroll
            for (int g=0; g<2; g++){
                int k0 = 16*g + 2*m;
                #pragma unroll
                for (int q=0; q<2; q++){
                    int c = k0 + q*8;
                    float wa = w1s[c], wb = w1s[c+1], ba = b1s[c], bb = b1s[c+1];
                    float p00 = fmaxf(fmaf(x0,wa,ba),0.f), p01 = fmaxf(fmaf(x0,wb,bb),0.f);
                    float p10 = fmaxf(fmaf(x1,wa,ba),0.f), p11 = fmaxf(fmaf(x1,wb,bb),0.f);
                    Ah[g][q*2]   = pack_hi(p00,p01);
                    Ah[g][q*2+1] = pack_hi(p10,p11);
                }
            }
        }

        const float* bias = smf + BIAS_F;
        run_layer<2,8 >(sv+O2, bias+0,   Ah, C, lane);
        conv_act<8>(C, Ah);
        run_layer<4,8 >(sv+O3, bias+64,  Ah, C, lane);
        conv_act<8>(C, Ah);
        run_layer<4,8 >(sv+O4, bias+128, Ah, C, lane);
        conv_act<8>(C, Ah);
        run_layer<4,16>(sv+O5, bias+192, Ah, C, lane);
        conv_act<16>(C, Ah);
        run_layer<8,16>(sv+O6, bias+320, Ah, C, lane);

        bool uni = __all_sync(FULL, v0r && v1r);
        int bf_ = __shfl_sync(FULL, b0i, 0);
        uni = uni && __all_sync(FULL, (b0i==bf_) && (b1i==bf_));
        if (uni){
            float* dst = d_sums + (size_t)bf_*128;
            #pragma unroll
            for (int f=0; f<16; f++){
                float s0 = fmaxf(C[f][0],0.f) + fmaxf(C[f][2],0.f);
                float s1 = fmaxf(C[f][1],0.f) + fmaxf(C[f][3],0.f);
                s0 += __shfl_xor_sync(FULL,s0,4);  s1 += __shfl_xor_sync(FULL,s1,4);
                s0 += __shfl_xor_sync(FULL,s0,8);  s1 += __shfl_xor_sync(FULL,s1,8);
                s0 += __shfl_xor_sync(FULL,s0,16); s1 += __shfl_xor_sync(FULL,s1,16);
                if (lane < 4){
                    atomicAdd(dst + f*8 + 2*lane,     s0);
                    atomicAdd(dst + f*8 + 2*lane + 1, s1);
                }
            }
            if (lane==0) atomicAdd(&d_cnts[bf_], 16.f);
        } else {
            unsigned vb0 = __ballot_sync(FULL, v0r && m==0);
            unsigned vb1 = __ballot_sync(FULL, v1r && m==0);
            unsigned rem = 0;
            #pragma unroll
            for (int rr=0; rr<8; rr++){
                if ((vb0>>(4*rr))&1) rem |= 1u<<rr;
                if ((vb1>>(4*rr))&1) rem |= 1u<<(rr+8);
            }
            while (rem){
                int j = __ffs(rem)-1;
                int bt = (j<8) ? __shfl_sync(FULL,b0i,j*4) : __shfl_sync(FULL,b1i,(j-8)*4);
                bool p0 = (b0i==bt), p1 = (b1i==bt);
                float* dst = d_sums + (size_t)bt*128;
                #pragma unroll
                for (int f=0; f<16; f++){
                    float s0 = (p0?fmaxf(C[f][0],0.f):0.f) + (p1?fmaxf(C[f][2],0.f):0.f);
                    float s1 = (p0?fmaxf(C[f][1],0.f):0.f) + (p1?fmaxf(C[f][3],0.f):0.f);
                    s0 += __shfl_xor_sync(FULL,s0,4);  s1 += __shfl_xor_sync(FULL,s1,4);
                    s0 += __shfl_xor_sync(FULL,s0,8);  s1 += __shfl_xor_sync(FULL,s1,8);
                    s0 += __shfl_xor_sync(FULL,s0,16); s1 += __shfl_xor_sync(FULL,s1,16);
                    if (lane < 4){
                        atomicAdd(dst + f*8 + 2*lane,     s0);
                        atomicAdd(dst + f*8 + 2*lane + 1, s1);
                    }
                }
                unsigned m0 = __ballot_sync(FULL, p0 && m==0);
                unsigned m1 = __ballot_sync(FULL, p1 && m==0);
                if (lane==0) atomicAdd(&d_cnts[bt], (float)(__popc(m0)+__popc(m1)));
                unsigned clr = 0;
                #pragma unroll
                for (int rr=0; rr<8; rr++){
                    if ((m0>>(4*rr))&1) clr |= 1u<<rr;
                    if ((m1>>(4*rr))&1) clr |= 1u<<(rr+8);
                }
                rem &= ~clr;
            }
        }
    }
}

// ================= graph-level MLP: persistent, warp per row =================
__global__ void __launch_bounds__(256,2)
graph_kernel(float* __restrict__ out)
{
    __shared__ float sF1[128*64];
    __shared__ float sFB1[64];
    __shared__ float sF2[64*32];
    __shared__ float sFB2[32];
    __shared__ float sF3[32*NCLS];
    __shared__ float sFB3[NCLS];
    __shared__ float sG0[128];

    int tid = threadIdx.x, lane = tid&31, w = tid>>5;
    for (int i=tid;i<128*64;i+=256) sF1[i]=d_F1[i];
    for (int i=tid;i<64;i+=256)     sFB1[i]=d_FB1[i];
    for (int i=tid;i<64*32;i+=256)  sF2[i]=d_F2[i];
    for (int i=tid;i<32;i+=256)     sFB2[i]=d_FB2[i];
    for (int i=tid;i<32*NCLS;i+=256) sF3[i]=d_F3[i];
    for (int i=tid;i<NCLS;i+=256)   sFB3[i]=d_FB3[i];
    for (int i=tid;i<128;i+=256)    sG0[i]=d_g0[i];
    __syncthreads();

    const unsigned FULL = 0xffffffffu;
    for (int row = blockIdx.x*8 + w; row < BGR; row += gridDim.x*8){
        float cnt = d_cnts[row];
        bool nz = cnt > 0.5f;
        float inv = nz ? 1.f/cnt : 0.f;

        float g[4];
        {
            float4 s4 = ((const float4*)(d_sums + (size_t)row*128))[lane];
            if (nz){ g[0]=s4.x*inv; g[1]=s4.y*inv; g[2]=s4.z*inv; g[3]=s4.w*inv; }
            else { float4 g4 = ((const float4*)sG0)[lane]; g[0]=g4.x; g[1]=g4.y; g[2]=g4.z; g[3]=g4.w; }
        }
        float za = sFB1[lane], zb = sFB1[lane+32];
        #pragma unroll
        for (int k4=0;k4<32;k4++){
            #pragma unroll
            for (int i=0;i<4;i++){
                float gk = __shfl_sync(FULL, g[i], k4);
                int k = k4*4+i;
                za = fmaf(gk, sF1[k*64+lane],    za);
                zb = fmaf(gk, sF1[k*64+lane+32], zb);
            }
        }
        float h1a = fmaxf(za,0.f), h1b = fmaxf(zb,0.f);
        float z2 = sFB2[lane];
        #pragma unroll
        for (int k=0;k<32;k++){
            float hk = __shfl_sync(FULL, h1a, k);
            z2 = fmaf(hk, sF2[k*32+lane], z2);
        }
        #pragma unroll
        for (int k=0;k<32;k++){
            float hk = __shfl_sync(FULL, h1b, k);
            z2 = fmaf(hk, sF2[(k+32)*32+lane], z2);
        }
        float h2 = fmaxf(z2,0.f);
        float o[NCLS];
        #pragma unroll
        for (int c=0;c<NCLS;c++) o[c] = h2 * sF3[lane*NCLS+c];
        #pragma unroll
        for (int c=0;c<NCLS;c++){
            o[c] += __shfl_xor_sync(FULL,o[c],16);
            o[c] += __shfl_xor_sync(FULL,o[c],8);
            o[c] += __shfl_xor_sync(FULL,o[c],4);
            o[c] += __shfl_xor_sync(FULL,o[c],2);
            o[c] += __shfl_xor_sync(FULL,o[c],1);
        }
        if (lane==0){
            #pragma unroll
            for (int c=0;c<NCLS;c++) out[row*NCLS+c] = o[c] + sFB3[c];
        }
    }
}

// ================= launch =================
extern "C" void kernel_launch(void* const* d_in, const int* in_sizes, int n_in,
                              void* d_out, int out_size)
{
    const float* x     = (const float*)d_in[0];
    const int*   batch = (const int*)d_in[1];
    int n = in_sizes[0];

    cudaFuncSetAttribute(node_kernel, cudaFuncAttributeMaxDynamicSharedMemorySize, NODE_SMEM_BYTES);

    prep_kernel<<<1,256>>>(
        (const float*)d_in[3],  (const float*)d_in[4],  (const float*)d_in[5],
        (const float*)d_in[6],  (const float*)d_in[7],  (const float*)d_in[8],
        (const float*)d_in[9],  (const float*)d_in[10],
        (const float*)d_in[11], (const float*)d_in[12], (const float*)d_in[13],
        (const float*)d_in[14], (const float*)d_in[15],
        (const float*)d_in[16], (const float*)d_in[17], (const float*)d_in[18],
        (const float*)d_in[19], (const float*)d_in[20], (const float*)d_in[21],
        (const float*)d_in[22], (const float*)d_in[23], (const float*)d_in[24],
        (const float*)d_in[25], (const float*)d_in[26]);
    pack_kernel<<<1,256>>>();
    zero_kernel<<<(BGR*128 + 255)/256, 256>>>();
    node_kernel<<<148, NTHR, NODE_SMEM_BYTES>>>(x, batch, n);
    graph_kernel<<<148, 256>>>((float*)d_out);
}

// round 16
// speedup vs baseline: 2.1390x; 1.4787x over previous
#include <cuda_runtime.h>
#include <cuda_bf16.h>
#include <cuda_fp16.h>
#include <cstdint>

#define EPSV 1e-5f
#define BGR 4096
#define NCLS 7
#define NTHR 384
typedef unsigned long long u64;
typedef unsigned int u32;

// ================= device globals =================
__device__ float d_w1[32], d_b1[32];
__device__ float d_W2[32*64],   d_B2[64];
__device__ float d_W3[64*64],   d_B3[64];
__device__ float d_W4[64*64],   d_B4[64];
__device__ float d_W5T[128*64], d_B5[128];   // [out(128)][in(64)]
__device__ float d_W6[128*128], d_B6[128];
__device__ float d_F1[128*64],  d_FB1[64];
__device__ float d_F2[64*32],   d_FB2[32];
__device__ float d_F3[32*NCLS], d_FB3[NCLS];
__device__ float d_g0[128];
__device__ float d_sums[BGR*128];
__device__ float d_cnts[BGR];

// fp16 fragment streams: per (kf,nf,lane) one u64 = {b0,b1} regs of mma B-frag
__device__ u64 g_S2[512];    // K=32 (KF=2),  N=64 (NF=8)
__device__ u64 g_S3[1024];   // K=64, N=64
__device__ u64 g_S4[1024];   // K=64, N=64
__device__ u64 g_S5[2048];   // K=64, N=128
__device__ u64 g_S6[4096];   // K=128, N=128

__device__ __forceinline__ float bn_a(const float* bn, int c, int i){ return bn[0*c+i]*rsqrtf(bn[3*c+i]+EPSV); }
__device__ __forceinline__ float bn_c(const float* bn, int c, int i, float a){ return bn[1*c+i]-bn[2*c+i]*a; }

// ================= prep: fold BNs (fp32, validated) =================
__global__ void prep_kernel(
    const float* w1, const float* b1, const float* bn1,
    const float* w2, const float* b2, const float* bn2,
    const float* c1aw, const float* c1ab,
    const float* c1bw, const float* c1bb, const float* cbn1,
    const float* c2aw, const float* c2ab,
    const float* c2bw, const float* c2bb, const float* cbn2,
    const float* f1w, const float* f1b, const float* fbn1,
    const float* f2w, const float* f2b, const float* fbn2,
    const float* f3w, const float* f3b)
{
    int t = threadIdx.x;
    for (int i=t;i<32;i+=256){ d_w1[i]=w1[i]; d_b1[i]=b1[i]; }
    for (int i=t;i<32*64;i+=256){ int k=i>>6; d_W2[i]=bn_a(bn1,32,k)*w2[i]; }
    for (int j=t;j<64;j+=256){ float s=b2[j];
        for(int k=0;k<32;k++){float a=bn_a(bn1,32,k); s+=bn_c(bn1,32,k,a)*w2[k*64+j];}
        d_B2[j]=s; }
    for (int i=t;i<64*64;i+=256){ int k=i>>6; d_W3[i]=bn_a(bn2,64,k)*c1aw[i]; }
    for (int j=t;j<64;j+=256){ float s=c1ab[j];
        for(int k=0;k<64;k++){float a=bn_a(bn2,64,k); s+=bn_c(bn2,64,k,a)*c1aw[k*64+j];}
        d_B3[j]=s; }
    for (int i=t;i<64*64;i+=256) d_W4[i]=c1bw[i];
    for (int j=t;j<64;j+=256)    d_B4[j]=c1bb[j];
    for (int i=t;i<128*64;i+=256){ int k=i>>6, m=i&63; d_W5T[i]=bn_a(cbn1,64,m)*c2aw[m*128+k]; }
    for (int k=t;k<128;k+=256){ float s=c2ab[k];
        for(int m=0;m<64;m++){float a=bn_a(cbn1,64,m); s+=bn_c(cbn1,64,m,a)*c2aw[m*128+k];}
        d_B5[k]=s; }
    for (int i=t;i<128*128;i+=256) d_W6[i]=c2bw[i];
    for (int j=t;j<128;j+=256)     d_B6[j]=c2bb[j];
    for (int i=t;i<128*64;i+=256){ int k=i>>6; d_F1[i]=bn_a(cbn2,128,k)*f1w[i]; }
    for (int j=t;j<64;j+=256){ float s=f1b[j];
        for(int k=0;k<128;k++){float a=bn_a(cbn2,128,k); s+=bn_c(cbn2,128,k,a)*f1w[k*64+j];}
        d_FB1[j]=s; }
    for (int k=t;k<128;k+=256){ float a=bn_a(cbn2,128,k); d_g0[k]=-bn_c(cbn2,128,k,a)/a; }
    for (int i=t;i<64*32;i+=256){ int k=i>>5; d_F2[i]=bn_a(fbn1,64,k)*f2w[i]; }
    for (int j=t;j<32;j+=256){ float s=f2b[j];
        for(int k=0;k<64;k++){float a=bn_a(fbn1,64,k); s+=bn_c(fbn1,64,k,a)*f2w[k*32+j];}
        d_FB2[j]=s; }
    for (int i=t;i<32*NCLS;i+=256){ int k=i/NCLS; d_F3[i]=bn_a(fbn2,32,k)*f3w[i]; }
    for (int j=t;j<NCLS;j+=256){ float s=f3b[j];
        for(int k=0;k<32;k++){float a=bn_a(fbn2,32,k); s+=bn_c(fbn2,32,k,a)*f3w[k*NCLS+j];}
        d_FB3[j]=s; }
}

// ================= pack: weights -> fp16 B-fragment streams =================
__device__ __forceinline__ u32 pkh(float a, float b){
    __half2 h = __floats2half2_rn(a, b);
    return *(u32*)&h;
}
__device__ void pack_stream(u64* S, const float* W, int KF, int NF, int N,
                            bool tr, int ld, int tid, int nthr)
{
    int tot = KF*NF*32;
    for (int i=tid;i<tot;i+=nthr){
        int lane = i&31, nf=(i>>5)%NF, kf=i/(32*NF);
        int nn = nf*8 + (lane>>2);
        int k0 = kf*16 + (lane&3)*2;
        float v[4];
        int ks[4]={k0,k0+1,k0+8,k0+9};
        #pragma unroll
        for (int j=0;j<4;j++) v[j] = tr ? W[nn*ld + ks[j]] : W[ks[j]*N + nn];
        u32 h0 = pkh(v[0],v[1]), h1 = pkh(v[2],v[3]);
        S[(kf*NF+nf)*32+lane] = (u64)h0 | ((u64)h1<<32);
    }
}
__global__ void pack_kernel(){
    int t = threadIdx.x;
    pack_stream(g_S2, d_W2,  2, 8,  64, false, 0,  t,256);
    pack_stream(g_S3, d_W3,  4, 8,  64, false, 0,  t,256);
    pack_stream(g_S4, d_W4,  4, 8,  64, false, 0,  t,256);
    pack_stream(g_S5, d_W5T, 4,16, 128, true, 64,  t,256);
    pack_stream(g_S6, d_W6,  8,16, 128, false, 0,  t,256);
}

__global__ void zero_kernel(){
    int i = blockIdx.x*blockDim.x + threadIdx.x;
    if (i < BGR*128) d_sums[i] = 0.f;
    if (i < BGR)     d_cnts[i] = 0.f;
}

// ================= node kernel =================
// SMEM layout (u64 element index for streams, then fp32)
#define O2 0
#define O3 512
#define O4 1536
#define O5 2560
#define O6 4608
#define SMV 8704                       // total u64 elements = 69632 B
#define BIAS_F (SMV*2)                 // float index 17408
#define W1_F   (BIAS_F+448)
#define NODE_SMEM_BYTES ((W1_F+64)*4)  // ~71.6 KB

__device__ __forceinline__ void mma_f16(float& c0,float& c1,float& c2,float& c3,
                                        u32 a0,u32 a1,u32 a2,u32 a3, u32 b0, u32 b1){
    asm volatile("mma.sync.aligned.m16n8k16.row.col.f32.f16.f16.f32 "
        "{%0,%1,%2,%3},{%4,%5,%6,%7},{%8,%9},{%0,%1,%2,%3};"
        : "+f"(c0),"+f"(c1),"+f"(c2),"+f"(c3)
        : "r"(a0),"r"(a1),"r"(a2),"r"(a3),"r"(b0),"r"(b1));
}

// single fp16 pass; nf in groups of 4 so same-accumulator MMAs are >=4 apart.
template<int KF,int NF>
__device__ __forceinline__ void run_layer(const u64* __restrict__ S,
    const float* __restrict__ bias, const u32 Ah[][4], float C[][4], int lane)
{
    int m2 = (lane&3)*2;
    #pragma unroll
    for (int nf=0;nf<NF;nf++){
        float2 bv = *(const float2*)(bias + nf*8 + m2);
        C[nf][0]=bv.x; C[nf][1]=bv.y; C[nf][2]=bv.x; C[nf][3]=bv.y;
    }
    #pragma unroll
    for (int kf=0;kf<KF;kf++){
        #pragma unroll
        for (int nf0=0;nf0<NF;nf0+=4){
            u64 f[4];
            #pragma unroll
            for (int j=0;j<4;j++) f[j] = S[(kf*NF+nf0+j)*32+lane];
            #pragma unroll
            for (int j=0;j<4;j++){
                int nf=nf0+j;
                mma_f16(C[nf][0],C[nf][1],C[nf][2],C[nf][3],
                        Ah[kf][0],Ah[kf][1],Ah[kf][2],Ah[kf][3],
                        (u32)f[j],(u32)(f[j]>>32));
            }
        }
    }
}

template<int NF>
__device__ __forceinline__ void conv_act(const float C[][4], u32 Ah[][4]){
    #pragma unroll
    for (int g=0;g<NF/2;g++){
        #pragma unroll
        for (int h=0;h<2;h++){
            float v0 = fmaxf(C[2*g][2*h],0.f),   v1 = fmaxf(C[2*g][2*h+1],0.f);
            float w0 = fmaxf(C[2*g+1][2*h],0.f), w1 = fmaxf(C[2*g+1][2*h+1],0.f);
            Ah[g][h]   = pkh(v0,v1);
            Ah[g][2+h] = pkh(w0,w1);
        }
    }
}

__global__ void __launch_bounds__(NTHR,1)
node_kernel(const float* __restrict__ x, const int* __restrict__ batch, int n)
{
    extern __shared__ float smf[];
    u64* sv = (u64*)smf;
    int tid = threadIdx.x;
    int lane = tid & 31, w = tid >> 5;

    // load streams + biases once
    for (int i=tid;i<512;i+=NTHR)  sv[O2+i]=g_S2[i];
    for (int i=tid;i<1024;i+=NTHR){ sv[O3+i]=g_S3[i]; sv[O4+i]=g_S4[i]; }
    for (int i=tid;i<2048;i+=NTHR) sv[O5+i]=g_S5[i];
    for (int i=tid;i<4096;i+=NTHR) sv[O6+i]=g_S6[i];
    { float* bias = smf + BIAS_F;
      for (int i=tid;i<64;i+=NTHR){ bias[i]=d_B2[i]; bias[64+i]=d_B3[i]; bias[128+i]=d_B4[i]; }
      for (int i=tid;i<128;i+=NTHR){ bias[192+i]=d_B5[i]; bias[320+i]=d_B6[i]; }
      float* w1s = smf + W1_F;
      for (int i=tid;i<32;i+=NTHR){ w1s[i]=d_w1[i]; w1s[32+i]=d_b1[i]; } }
    __syncthreads();

    const unsigned FULL = 0xffffffffu;
    int r = lane>>2, m = lane&3;

    // static warp-level task assignment: 16 rows per task, no barriers
    const int ntasks = (n + 15) >> 4;
    const int nwarps = gridDim.x * (NTHR/32);
    int gw = blockIdx.x * (NTHR/32) + w;

    for (int task = gw; task < ntasks; task += nwarps){
        int e0 = task*16 + r, e1 = e0 + 8;
        bool v0r = e0 < n, v1r = e1 < n;
        float x0 = v0r ? x[e0] : 0.f;
        float x1 = v1r ? x[e1] : 0.f;
        int b0i = v0r ? batch[e0] : -1;
        int b1i = v1r ? batch[e1] : -1;

        u32 Ah[8][4];
        float C[16][4];

        // --- layer1: 1 -> 32 directly into A-fragments (KF=2), fp16 ---
        {
            const float* w1s = smf + W1_F;
            const float* b1s = w1s + 32;
            #pragma unroll
            for (int g=0; g<2; g++){
                int k0 = 16*g + 2*m;
                #pragma unroll
                for (int q=0; q<2; q++){
                    int c = k0 + q*8;
                    float wa = w1s[c], wb = w1s[c+1], ba = b1s[c], bb = b1s[c+1];
                    float p00 = fmaxf(fmaf(x0,wa,ba),0.f), p01 = fmaxf(fmaf(x0,wb,bb),0.f);
                    float p10 = fmaxf(fmaf(x1,wa,ba),0.f), p11 = fmaxf(fmaf(x1,wb,bb),0.f);
                    Ah[g][q*2]   = pkh(p00,p01);
                    Ah[g][q*2+1] = pkh(p10,p11);
                }
            }
        }

        const float* bias = smf + BIAS_F;
        run_layer<2,8 >(sv+O2, bias+0,   Ah, C, lane);
        conv_act<8>(C, Ah);
        run_layer<4,8 >(sv+O3, bias+64,  Ah, C, lane);
        conv_act<8>(C, Ah);
        run_layer<4,8 >(sv+O4, bias+128, Ah, C, lane);
        conv_act<8>(C, Ah);
        run_layer<4,16>(sv+O5, bias+192, Ah, C, lane);
        conv_act<16>(C, Ah);
        run_layer<8,16>(sv+O6, bias+320, Ah, C, lane);

        // --- relu + segment reduction (rows r, r+8 per lane) ---
        bool uni = __all_sync(FULL, v0r && v1r);
        int bf_ = __shfl_sync(FULL, b0i, 0);
        uni = uni && __all_sync(FULL, (b0i==bf_) && (b1i==bf_));
        if (uni){
            float* dst = d_sums + (size_t)bf_*128;
            #pragma unroll
            for (int f=0; f<16; f++){
                float s0 = fmaxf(C[f][0],0.f) + fmaxf(C[f][2],0.f);
                float s1 = fmaxf(C[f][1],0.f) + fmaxf(C[f][3],0.f);
                s0 += __shfl_xor_sync(FULL,s0,4);  s1 += __shfl_xor_sync(FULL,s1,4);
                s0 += __shfl_xor_sync(FULL,s0,8);  s1 += __shfl_xor_sync(FULL,s1,8);
                s0 += __shfl_xor_sync(FULL,s0,16); s1 += __shfl_xor_sync(FULL,s1,16);
                if (lane < 4){
                    atomicAdd(dst + f*8 + 2*lane,     s0);
                    atomicAdd(dst + f*8 + 2*lane + 1, s1);
                }
            }
            if (lane==0) atomicAdd(&d_cnts[bf_], 16.f);
        } else {
            unsigned vb0 = __ballot_sync(FULL, v0r && m==0);
            unsigned vb1 = __ballot_sync(FULL, v1r && m==0);
            unsigned rem = 0;
            #pragma unroll
            for (int rr=0; rr<8; rr++){
                if ((vb0>>(4*rr))&1) rem |= 1u<<rr;
                if ((vb1>>(4*rr))&1) rem |= 1u<<(rr+8);
            }
            while (rem){
                int j = __ffs(rem)-1;
                int bt = (j<8) ? __shfl_sync(FULL,b0i,j*4) : __shfl_sync(FULL,b1i,(j-8)*4);
                bool p0 = (b0i==bt), p1 = (b1i==bt);
                float* dst = d_sums + (size_t)bt*128;
                #pragma unroll
                for (int f=0; f<16; f++){
                    float s0 = (p0?fmaxf(C[f][0],0.f):0.f) + (p1?fmaxf(C[f][2],0.f):0.f);
                    float s1 = (p0?fmaxf(C[f][1],0.f):0.f) + (p1?fmaxf(C[f][3],0.f):0.f);
                    s0 += __shfl_xor_sync(FULL,s0,4);  s1 += __shfl_xor_sync(FULL,s1,4);
                    s0 += __shfl_xor_sync(FULL,s0,8);  s1 += __shfl_xor_sync(FULL,s1,8);
                    s0 += __shfl_xor_sync(FULL,s0,16); s1 += __shfl_xor_sync(FULL,s1,16);
                    if (lane < 4){
                        atomicAdd(dst + f*8 + 2*lane,     s0);
                        atomicAdd(dst + f*8 + 2*lane + 1, s1);
                    }
                }
                unsigned m0 = __ballot_sync(FULL, p0 && m==0);
                unsigned m1 = __ballot_sync(FULL, p1 && m==0);
                if (lane==0) atomicAdd(&d_cnts[bt], (float)(__popc(m0)+__popc(m1)));
                unsigned clr = 0;
                #pragma unroll
                for (int rr=0; rr<8; rr++){
                    if ((m0>>(4*rr))&1) clr |= 1u<<rr;
                    if ((m1>>(4*rr))&1) clr |= 1u<<(rr+8);
                }
                rem &= ~clr;
            }
        }
    }
}

// ================= graph-level MLP: persistent, warp per row (fp32, unchanged) =================
__global__ void __launch_bounds__(256,2)
graph_kernel(float* __restrict__ out)
{
    __shared__ float sF1[128*64];
    __shared__ float sFB1[64];
    __shared__ float sF2[64*32];
    __shared__ float sFB2[32];
    __shared__ float sF3[32*NCLS];
    __shared__ float sFB3[NCLS];
    __shared__ float sG0[128];

    int tid = threadIdx.x, lane = tid&31, w = tid>>5;
    for (int i=tid;i<128*64;i+=256) sF1[i]=d_F1[i];
    for (int i=tid;i<64;i+=256)     sFB1[i]=d_FB1[i];
    for (int i=tid;i<64*32;i+=256)  sF2[i]=d_F2[i];
    for (int i=tid;i<32;i+=256)     sFB2[i]=d_FB2[i];
    for (int i=tid;i<32*NCLS;i+=256) sF3[i]=d_F3[i];
    for (int i=tid;i<NCLS;i+=256)   sFB3[i]=d_FB3[i];
    for (int i=tid;i<128;i+=256)    sG0[i]=d_g0[i];
    __syncthreads();

    const unsigned FULL = 0xffffffffu;
    for (int row = blockIdx.x*8 + w; row < BGR; row += gridDim.x*8){
        float cnt = d_cnts[row];
        bool nz = cnt > 0.5f;
        float inv = nz ? 1.f/cnt : 0.f;

        float g[4];
        {
            float4 s4 = ((const float4*)(d_sums + (size_t)row*128))[lane];
            if (nz){ g[0]=s4.x*inv; g[1]=s4.y*inv; g[2]=s4.z*inv; g[3]=s4.w*inv; }
            else { float4 g4 = ((const float4*)sG0)[lane]; g[0]=g4.x; g[1]=g4.y; g[2]=g4.z; g[3]=g4.w; }
        }
        float za = sFB1[lane], zb = sFB1[lane+32];
        #pragma unroll
        for (int k4=0;k4<32;k4++){
            #pragma unroll
            for (int i=0;i<4;i++){
                float gk = __shfl_sync(FULL, g[i], k4);
                int k = k4*4+i;
                za = fmaf(gk, sF1[k*64+lane],    za);
                zb = fmaf(gk, sF1[k*64+lane+32], zb);
            }
        }
        float h1a = fmaxf(za,0.f), h1b = fmaxf(zb,0.f);
        float z2 = sFB2[lane];
        #pragma unroll
        for (int k=0;k<32;k++){
            float hk = __shfl_sync(FULL, h1a, k);
            z2 = fmaf(hk, sF2[k*32+lane], z2);
        }
        #pragma unroll
        for (int k=0;k<32;k++){
            float hk = __shfl_sync(FULL, h1b, k);
            z2 = fmaf(hk, sF2[(k+32)*32+lane], z2);
        }
        float h2 = fmaxf(z2,0.f);
        float o[NCLS];
        #pragma unroll
        for (int c=0;c<NCLS;c++) o[c] = h2 * sF3[lane*NCLS+c];
        #pragma unroll
        for (int c=0;c<NCLS;c++){
            o[c] += __shfl_xor_sync(FULL,o[c],16);
            o[c] += __shfl_xor_sync(FULL,o[c],8);
            o[c] += __shfl_xor_sync(FULL,o[c],4);
            o[c] += __shfl_xor_sync(FULL,o[c],2);
            o[c] += __shfl_xor_sync(FULL,o[c],1);
        }
        if (lane==0){
            #pragma unroll
            for (int c=0;c<NCLS;c++) out[row*NCLS+c] = o[c] + sFB3[c];
        }
    }
}

// ================= launch =================
extern "C" void kernel_launch(void* const* d_in, const int* in_sizes, int n_in,
                              void* d_out, int out_size)
{
    const float* x     = (const float*)d_in[0];
    const int*   batch = (const int*)d_in[1];
    int n = in_sizes[0];

    cudaFuncSetAttribute(node_kernel, cudaFuncAttributeMaxDynamicSharedMemorySize, NODE_SMEM_BYTES);

    prep_kernel<<<1,256>>>(
        (const float*)d_in[3],  (const float*)d_in[4],  (const float*)d_in[5],
        (const float*)d_in[6],  (const float*)d_in[7],  (const float*)d_in[8],
        (const float*)d_in[9],  (const float*)d_in[10],
        (const float*)d_in[11], (const float*)d_in[12], (const float*)d_in[13],
        (const float*)d_in[14], (const float*)d_in[15],
        (const float*)d_in[16], (const float*)d_in[17], (const float*)d_in[18],
        (const float*)d_in[19], (const float*)d_in[20], (const float*)d_in[21],
        (const float*)d_in[22], (const float*)d_in[23], (const float*)d_in[24],
        (const float*)d_in[25], (const float*)d_in[26]);
    pack_kernel<<<1,256>>>();
    zero_kernel<<<(BGR*128 + 255)/256, 256>>>();
    node_kernel<<<148, NTHR, NODE_SMEM_BYTES>>>(x, batch, n);
    graph_kernel<<<148, 256>>>((float*)d_out);
}

// round 17
// speedup vs baseline: 2.1768x; 1.0177x over previous
#include <cuda_runtime.h>
#include <cuda_bf16.h>
#include <cuda_fp16.h>
#include <cstdint>

#define EPSV 1e-5f
#define BGR 4096
#define NCLS 7
#define NTHR 512
typedef unsigned long long u64;
typedef unsigned int u32;

// ================= device globals =================
__device__ float d_w1[32], d_b1[32];
__device__ float d_W2[32*64],   d_B2[64];
__device__ float d_W3[64*64],   d_B3[64];
__device__ float d_W4[64*64],   d_B4[64];
__device__ float d_W5T[128*64], d_B5[128];   // [out(128)][in(64)]
__device__ float d_W6[128*128], d_B6[128];
__device__ float d_F1[128*64],  d_FB1[64];
__device__ float d_F2[64*32],   d_FB2[32];
__device__ float d_F3[32*NCLS], d_FB3[NCLS];
__device__ float d_g0[128];
__device__ float d_sums[BGR*128];
__device__ float d_cnts[BGR];

// fp16 fragment streams: per (kf,nf,lane) one u64 = {b0,b1} regs of mma B-frag
__device__ u64 g_S2[512];    // K=32 (KF=2),  N=64 (NF=8)
__device__ u64 g_S3[1024];   // K=64, N=64
__device__ u64 g_S4[1024];   // K=64, N=64
__device__ u64 g_S5[2048];   // K=64, N=128
__device__ u64 g_S6[4096];   // K=128, N=128

__device__ __forceinline__ float bn_a(const float* bn, int c, int i){ return bn[0*c+i]*rsqrtf(bn[3*c+i]+EPSV); }
__device__ __forceinline__ float bn_c(const float* bn, int c, int i, float a){ return bn[1*c+i]-bn[2*c+i]*a; }

__device__ __forceinline__ u32 pkh(float a, float b){
    __half2 h = __floats2half2_rn(a, b);
    return *(u32*)&h;
}
__device__ void pack_stream(u64* S, const float* W, int KF, int NF, int N,
                            bool tr, int ld, int tid, int nthr)
{
    int tot = KF*NF*32;
    for (int i=tid;i<tot;i+=nthr){
        int lane = i&31, nf=(i>>5)%NF, kf=i/(32*NF);
        int nn = nf*8 + (lane>>2);
        int k0 = kf*16 + (lane&3)*2;
        float v[4];
        int ks[4]={k0,k0+1,k0+8,k0+9};
        #pragma unroll
        for (int j=0;j<4;j++) v[j] = tr ? W[nn*ld + ks[j]] : W[ks[j]*N + nn];
        u32 h0 = pkh(v[0],v[1]), h1 = pkh(v[2],v[3]);
        S[(kf*NF+nf)*32+lane] = (u64)h0 | ((u64)h1<<32);
    }
}

// ================= prep+pack merged: fold BNs then pack fragments =================
__global__ void prep_kernel(
    const float* w1, const float* b1, const float* bn1,
    const float* w2, const float* b2, const float* bn2,
    const float* c1aw, const float* c1ab,
    const float* c1bw, const float* c1bb, const float* cbn1,
    const float* c2aw, const float* c2ab,
    const float* c2bw, const float* c2bb, const float* cbn2,
    const float* f1w, const float* f1b, const float* fbn1,
    const float* f2w, const float* f2b, const float* fbn2,
    const float* f3w, const float* f3b)
{
    int t = threadIdx.x;
    for (int i=t;i<32;i+=256){ d_w1[i]=w1[i]; d_b1[i]=b1[i]; }
    for (int i=t;i<32*64;i+=256){ int k=i>>6; d_W2[i]=bn_a(bn1,32,k)*w2[i]; }
    for (int j=t;j<64;j+=256){ float s=b2[j];
        for(int k=0;k<32;k++){float a=bn_a(bn1,32,k); s+=bn_c(bn1,32,k,a)*w2[k*64+j];}
        d_B2[j]=s; }
    for (int i=t;i<64*64;i+=256){ int k=i>>6; d_W3[i]=bn_a(bn2,64,k)*c1aw[i]; }
    for (int j=t;j<64;j+=256){ float s=c1ab[j];
        for(int k=0;k<64;k++){float a=bn_a(bn2,64,k); s+=bn_c(bn2,64,k,a)*c1aw[k*64+j];}
        d_B3[j]=s; }
    for (int i=t;i<64*64;i+=256) d_W4[i]=c1bw[i];
    for (int j=t;j<64;j+=256)    d_B4[j]=c1bb[j];
    for (int i=t;i<128*64;i+=256){ int k=i>>6, m=i&63; d_W5T[i]=bn_a(cbn1,64,m)*c2aw[m*128+k]; }
    for (int k=t;k<128;k+=256){ float s=c2ab[k];
        for(int m=0;m<64;m++){float a=bn_a(cbn1,64,m); s+=bn_c(cbn1,64,m,a)*c2aw[m*128+k];}
        d_B5[k]=s; }
    for (int i=t;i<128*128;i+=256) d_W6[i]=c2bw[i];
    for (int j=t;j<128;j+=256)     d_B6[j]=c2bb[j];
    for (int i=t;i<128*64;i+=256){ int k=i>>6; d_F1[i]=bn_a(cbn2,128,k)*f1w[i]; }
    for (int j=t;j<64;j+=256){ float s=f1b[j];
        for(int k=0;k<128;k++){float a=bn_a(cbn2,128,k); s+=bn_c(cbn2,128,k,a)*f1w[k*64+j];}
        d_FB1[j]=s; }
    for (int k=t;k<128;k+=256){ float a=bn_a(cbn2,128,k); d_g0[k]=-bn_c(cbn2,128,k,a)/a; }
    for (int i=t;i<64*32;i+=256){ int k=i>>5; d_F2[i]=bn_a(fbn1,64,k)*f2w[i]; }
    for (int j=t;j<32;j+=256){ float s=f2b[j];
        for(int k=0;k<64;k++){float a=bn_a(fbn1,64,k); s+=bn_c(fbn1,64,k,a)*f2w[k*32+j];}
        d_FB2[j]=s; }
    for (int i=t;i<32*NCLS;i+=256){ int k=i/NCLS; d_F3[i]=bn_a(fbn2,32,k)*f3w[i]; }
    for (int j=t;j<NCLS;j+=256){ float s=f3b[j];
        for(int k=0;k<32;k++){float a=bn_a(fbn2,32,k); s+=bn_c(fbn2,32,k,a)*f3w[k*NCLS+j];}
        d_FB3[j]=s; }

    __syncthreads();
    pack_stream(g_S2, d_W2,  2, 8,  64, false, 0,  t,256);
    pack_stream(g_S3, d_W3,  4, 8,  64, false, 0,  t,256);
    pack_stream(g_S4, d_W4,  4, 8,  64, false, 0,  t,256);
    pack_stream(g_S5, d_W5T, 4,16, 128, true, 64,  t,256);
    pack_stream(g_S6, d_W6,  8,16, 128, false, 0,  t,256);
}

__global__ void zero_kernel(){
    int i = blockIdx.x*blockDim.x + threadIdx.x;
    if (i < BGR*128) d_sums[i] = 0.f;
    if (i < BGR)     d_cnts[i] = 0.f;
}

// ================= node kernel =================
// SMEM layout (u64 element index for streams, then fp32)
#define O2 0
#define O3 512
#define O4 1536
#define O5 2560
#define O6 4608
#define SMV 8704                       // total u64 elements = 69632 B
#define BIAS_F (SMV*2)                 // float index 17408
#define W1_F   (BIAS_F+448)
#define NODE_SMEM_BYTES ((W1_F+64)*4)  // ~71.6 KB

__device__ __forceinline__ void mma_f16(float& c0,float& c1,float& c2,float& c3,
                                        u32 a0,u32 a1,u32 a2,u32 a3, u32 b0, u32 b1){
    asm volatile("mma.sync.aligned.m16n8k16.row.col.f32.f16.f16.f32 "
        "{%0,%1,%2,%3},{%4,%5,%6,%7},{%8,%9},{%0,%1,%2,%3};"
        : "+f"(c0),"+f"(c1),"+f"(c2),"+f"(c3)
        : "r"(a0),"r"(a1),"r"(a2),"r"(a3),"r"(b0),"r"(b1));
}

__device__ __forceinline__ void initC8(float C[][4], const float* bias, int m2){
    #pragma unroll
    for (int nf=0;nf<8;nf++){
        float2 bv = *(const float2*)(bias + nf*8 + m2);
        C[nf][0]=bv.x; C[nf][1]=bv.y; C[nf][2]=bv.x; C[nf][3]=bv.y;
    }
}

// accumulate KF k-fragments x 8 nf-fragments into C (no init); stream row stride NFS.
template<int KF,int NFS>
__device__ __forceinline__ void acc8(const u64* __restrict__ S,
    const u32 A[][4], float C[][4], int lane)
{
    #pragma unroll
    for (int kf=0;kf<KF;kf++){
        #pragma unroll
        for (int nf0=0;nf0<8;nf0+=4){
            u64 f[4];
            #pragma unroll
            for (int j=0;j<4;j++) f[j] = S[(kf*NFS+nf0+j)*32+lane];
            #pragma unroll
            for (int j=0;j<4;j++){
                int nf=nf0+j;
                mma_f16(C[nf][0],C[nf][1],C[nf][2],C[nf][3],
                        A[kf][0],A[kf][1],A[kf][2],A[kf][3],
                        (u32)f[j],(u32)(f[j]>>32));
            }
        }
    }
}

// convert 8 C-fragments (64 cols) into 4 fp16 A-fragments
__device__ __forceinline__ void conv8(const float C[][4], u32 A[][4]){
    #pragma unroll
    for (int g=0;g<4;g++){
        #pragma unroll
        for (int h=0;h<2;h++){
            float v0 = fmaxf(C[2*g][2*h],0.f),   v1 = fmaxf(C[2*g][2*h+1],0.f);
            float w0 = fmaxf(C[2*g+1][2*h],0.f), w1 = fmaxf(C[2*g+1][2*h+1],0.f);
            A[g][h]   = pkh(v0,v1);
            A[g][2+h] = pkh(w0,w1);
        }
    }
}

// segment reduction over 8 C-fragments covering cols [colbase, colbase+64)
__device__ __forceinline__ void seg_reduce8(const float C[][4], bool v0r, bool v1r,
                                            int b0i, int b1i, int lane, int m,
                                            int colbase, bool addcnt)
{
    const unsigned FULL = 0xffffffffu;
    bool uni = __all_sync(FULL, v0r && v1r);
    int bf_ = __shfl_sync(FULL, b0i, 0);
    uni = uni && __all_sync(FULL, (b0i==bf_) && (b1i==bf_));
    if (uni){
        float* dst = d_sums + (size_t)bf_*128 + colbase;
        #pragma unroll
        for (int f=0; f<8; f++){
            float s0 = fmaxf(C[f][0],0.f) + fmaxf(C[f][2],0.f);
            float s1 = fmaxf(C[f][1],0.f) + fmaxf(C[f][3],0.f);
            s0 += __shfl_xor_sync(FULL,s0,4);  s1 += __shfl_xor_sync(FULL,s1,4);
            s0 += __shfl_xor_sync(FULL,s0,8);  s1 += __shfl_xor_sync(FULL,s1,8);
            s0 += __shfl_xor_sync(FULL,s0,16); s1 += __shfl_xor_sync(FULL,s1,16);
            if (lane < 4){
                atomicAdd(dst + f*8 + 2*lane,     s0);
                atomicAdd(dst + f*8 + 2*lane + 1, s1);
            }
        }
        if (addcnt && lane==0) atomicAdd(&d_cnts[bf_], 16.f);
    } else {
        unsigned vb0 = __ballot_sync(FULL, v0r && m==0);
        unsigned vb1 = __ballot_sync(FULL, v1r && m==0);
        unsigned rem = 0;
        #pragma unroll
        for (int rr=0; rr<8; rr++){
            if ((vb0>>(4*rr))&1) rem |= 1u<<rr;
            if ((vb1>>(4*rr))&1) rem |= 1u<<(rr+8);
        }
        while (rem){
            int j = __ffs(rem)-1;
            int bt = (j<8) ? __shfl_sync(FULL,b0i,j*4) : __shfl_sync(FULL,b1i,(j-8)*4);
            bool p0 = (b0i==bt), p1 = (b1i==bt);
            float* dst = d_sums + (size_t)bt*128 + colbase;
            #pragma unroll
            for (int f=0; f<8; f++){
                float s0 = (p0?fmaxf(C[f][0],0.f):0.f) + (p1?fmaxf(C[f][2],0.f):0.f);
                float s1 = (p0?fmaxf(C[f][1],0.f):0.f) + (p1?fmaxf(C[f][3],0.f):0.f);
                s0 += __shfl_xor_sync(FULL,s0,4);  s1 += __shfl_xor_sync(FULL,s1,4);
                s0 += __shfl_xor_sync(FULL,s0,8);  s1 += __shfl_xor_sync(FULL,s1,8);
                s0 += __shfl_xor_sync(FULL,s0,16); s1 += __shfl_xor_sync(FULL,s1,16);
                if (lane < 4){
                    atomicAdd(dst + f*8 + 2*lane,     s0);
                    atomicAdd(dst + f*8 + 2*lane + 1, s1);
                }
            }
            unsigned m0 = __ballot_sync(FULL, p0 && m==0);
            unsigned m1 = __ballot_sync(FULL, p1 && m==0);
            if (addcnt && lane==0) atomicAdd(&d_cnts[bt], (float)(__popc(m0)+__popc(m1)));
            unsigned clr = 0;
            #pragma unroll
            for (int rr=0; rr<8; rr++){
                if ((m0>>(4*rr))&1) clr |= 1u<<rr;
                if ((m1>>(4*rr))&1) clr |= 1u<<(rr+8);
            }
            rem &= ~clr;
        }
    }
}

__global__ void __launch_bounds__(NTHR,1)
node_kernel(const float* __restrict__ x, const int* __restrict__ batch, int n)
{
    extern __shared__ float smf[];
    u64* sv = (u64*)smf;
    int tid = threadIdx.x;
    int lane = tid & 31, w = tid >> 5;

    // load streams + biases once
    for (int i=tid;i<512;i+=NTHR)  sv[O2+i]=g_S2[i];
    for (int i=tid;i<1024;i+=NTHR){ sv[O3+i]=g_S3[i]; sv[O4+i]=g_S4[i]; }
    for (int i=tid;i<2048;i+=NTHR) sv[O5+i]=g_S5[i];
    for (int i=tid;i<4096;i+=NTHR) sv[O6+i]=g_S6[i];
    { float* bias = smf + BIAS_F;
      for (int i=tid;i<64;i+=NTHR){ bias[i]=d_B2[i]; bias[64+i]=d_B3[i]; bias[128+i]=d_B4[i]; }
      for (int i=tid;i<128;i+=NTHR){ bias[192+i]=d_B5[i]; bias[320+i]=d_B6[i]; }
      float* w1s = smf + W1_F;
      for (int i=tid;i<32;i+=NTHR){ w1s[i]=d_w1[i]; w1s[32+i]=d_b1[i]; } }
    __syncthreads();

    int r = lane>>2, m = lane&3;
    int m2 = m*2;

    // static warp-level task assignment: 16 rows per task, no barriers
    const int ntasks = (n + 15) >> 4;
    const int nwarps = gridDim.x * (NTHR/32);
    int gw = blockIdx.x * (NTHR/32) + w;

    for (int task = gw; task < ntasks; task += nwarps){
        int e0 = task*16 + r, e1 = e0 + 8;
        bool v0r = e0 < n, v1r = e1 < n;
        float x0 = v0r ? x[e0] : 0.f;
        float x1 = v1r ? x[e1] : 0.f;
        int b0i = v0r ? batch[e0] : -1;
        int b1i = v1r ? batch[e1] : -1;

        u32 P[2][4];     // layer1 output (KF=2)
        u32 Q[4][4];     // chain buffer
        u32 R_[4][4];    // chain buffer
        u32 AL[4][4], AH[4][4];   // L5 output halves (L6 input K=128)
        float C[8][4];

        // --- layer1: 1 -> 32 directly into A-fragments (KF=2), fp16 ---
        {
            const float* w1s = smf + W1_F;
            const float* b1s = w1s + 32;
            #pragma unroll
            for (int g=0; g<2; g++){
                int k0 = 16*g + m2;
                #pragma unroll
                for (int q=0; q<2; q++){
                    int c = k0 + q*8;
                    float wa = w1s[c], wb = w1s[c+1], ba = b1s[c], bb = b1s[c+1];
                    float p00 = fmaxf(fmaf(x0,wa,ba),0.f), p01 = fmaxf(fmaf(x0,wb,bb),0.f);
                    float p10 = fmaxf(fmaf(x1,wa,ba),0.f), p11 = fmaxf(fmaf(x1,wb,bb),0.f);
                    P[g][q*2]   = pkh(p00,p01);
                    P[g][q*2+1] = pkh(p10,p11);
                }
            }
        }

        const float* bias = smf + BIAS_F;
        // L2: 32->64
        initC8(C, bias+0, m2);
        acc8<2,8>(sv+O2, P, C, lane);
        conv8(C, Q);
        // L3: 64->64
        initC8(C, bias+64, m2);
        acc8<4,8>(sv+O3, Q, C, lane);
        conv8(C, R_);
        // L4: 64->64
        initC8(C, bias+128, m2);
        acc8<4,8>(sv+O4, R_, C, lane);
        conv8(C, Q);
        // L5: 64->128 in two N-halves
        initC8(C, bias+192, m2);
        acc8<4,16>(sv+O5, Q, C, lane);
        conv8(C, AL);
        initC8(C, bias+192+64, m2);
        acc8<4,16>(sv+O5 + 8*32, Q, C, lane);
        conv8(C, AH);
        // L6: 128->128 in two N-halves, fused segment reduction
        initC8(C, bias+320, m2);
        acc8<4,16>(sv+O6,           AL, C, lane);
        acc8<4,16>(sv+O6 + 64*32,   AH, C, lane);
        seg_reduce8(C, v0r, v1r, b0i, b1i, lane, m, 0, true);
        initC8(C, bias+320+64, m2);
        acc8<4,16>(sv+O6 + 8*32,         AL, C, lane);
        acc8<4,16>(sv+O6 + 64*32 + 8*32, AH, C, lane);
        seg_reduce8(C, v0r, v1r, b0i, b1i, lane, m, 64, false);
    }
}

// ================= graph-level MLP: persistent, warp per row (fp32, unchanged) =================
__global__ void __launch_bounds__(256,2)
graph_kernel(float* __restrict__ out)
{
    __shared__ float sF1[128*64];
    __shared__ float sFB1[64];
    __shared__ float sF2[64*32];
    __shared__ float sFB2[32];
    __shared__ float sF3[32*NCLS];
    __shared__ float sFB3[NCLS];
    __shared__ float sG0[128];

    int tid = threadIdx.x, lane = tid&31, w = tid>>5;
    for (int i=tid;i<128*64;i+=256) sF1[i]=d_F1[i];
    for (int i=tid;i<64;i+=256)     sFB1[i]=d_FB1[i];
    for (int i=tid;i<64*32;i+=256)  sF2[i]=d_F2[i];
    for (int i=tid;i<32;i+=256)     sFB2[i]=d_FB2[i];
    for (int i=tid;i<32*NCLS;i+=256) sF3[i]=d_F3[i];
    for (int i=tid;i<NCLS;i+=256)   sFB3[i]=d_FB3[i];
    for (int i=tid;i<128;i+=256)    sG0[i]=d_g0[i];
    __syncthreads();

    const unsigned FULL = 0xffffffffu;
    for (int row = blockIdx.x*8 + w; row < BGR; row += gridDim.x*8){
        float cnt = d_cnts[row];
        bool nz = cnt > 0.5f;
        float inv = nz ? 1.f/cnt : 0.f;

        float g[4];
        {
            float4 s4 = ((const float4*)(d_sums + (size_t)row*128))[lane];
            if (nz){ g[0]=s4.x*inv; g[1]=s4.y*inv; g[2]=s4.z*inv; g[3]=s4.w*inv; }
            else { float4 g4 = ((const float4*)sG0)[lane]; g[0]=g4.x; g[1]=g4.y; g[2]=g4.z; g[3]=g4.w; }
        }
        float za = sFB1[lane], zb = sFB1[lane+32];
        #pragma unroll
        for (int k4=0;k4<32;k4++){
            #pragma unroll
            for (int i=0;i<4;i++){
                float gk = __shfl_sync(FULL, g[i], k4);
                int k = k4*4+i;
                za = fmaf(gk, sF1[k*64+lane],    za);
                zb = fmaf(gk, sF1[k*64+lane+32], zb);
            }
        }
        float h1a = fmaxf(za,0.f), h1b = fmaxf(zb,0.f);
        float z2 = sFB2[lane];
        #pragma unroll
        for (int k=0;k<32;k++){
            float hk = __shfl_sync(FULL, h1a, k);
            z2 = fmaf(hk, sF2[k*32+lane], z2);
        }
        #pragma unroll
        for (int k=0;k<32;k++){
            float hk = __shfl_sync(FULL, h1b, k);
            z2 = fmaf(hk, sF2[(k+32)*32+lane], z2);
        }
        float h2 = fmaxf(z2,0.f);
        float o[NCLS];
        #pragma unroll
        for (int c=0;c<NCLS;c++) o[c] = h2 * sF3[lane*NCLS+c];
        #pragma unroll
        for (int c=0;c<NCLS;c++){
            o[c] += __shfl_xor_sync(FULL,o[c],16);
            o[c] += __shfl_xor_sync(FULL,o[c],8);
            o[c] += __shfl_xor_sync(FULL,o[c],4);
            o[c] += __shfl_xor_sync(FULL,o[c],2);
            o[c] += __shfl_xor_sync(FULL,o[c],1);
        }
        if (lane==0){
            #pragma unroll
            for (int c=0;c<NCLS;c++) out[row*NCLS+c] = o[c] + sFB3[c];
        }
    }
}

// ================= launch =================
extern "C" void kernel_launch(void* const* d_in, const int* in_sizes, int n_in,
                              void* d_out, int out_size)
{
    const float* x     = (const float*)d_in[0];
    const int*   batch = (const int*)d_in[1];
    int n = in_sizes[0];

    cudaFuncSetAttribute(node_kernel, cudaFuncAttributeMaxDynamicSharedMemorySize, NODE_SMEM_BYTES);

    prep_kernel<<<1,256>>>(
        (const float*)d_in[3],  (const float*)d_in[4],  (const float*)d_in[5],
        (const float*)d_in[6],  (const float*)d_in[7],  (const float*)d_in[8],
        (const float*)d_in[9],  (const float*)d_in[10],
        (const float*)d_in[11], (const float*)d_in[12], (const float*)d_in[13],
        (const float*)d_in[14], (const float*)d_in[15],
        (const float*)d_in[16], (const float*)d_in[17], (const float*)d_in[18],
        (const float*)d_in[19], (const float*)d_in[20], (const float*)d_in[21],
        (const float*)d_in[22], (const float*)d_in[23], (const float*)d_in[24],
        (const float*)d_in[25], (const float*)d_in[26]);
    zero_kernel<<<(BGR*128 + 255)/256, 256>>>();
    node_kernel<<<148, NTHR, NODE_SMEM_BYTES>>>(x, batch, n);
    graph_kernel<<<148, 256>>>((float*)d_out);
}